// round 1
// baseline (speedup 1.0000x reference)
#include <cuda_runtime.h>
#include <cstdint>
#include <cstddef>

#define GDIM 64
#define G3 (GDIM*GDIM*GDIM)
#define BATCH 4
#define NPTS 200000
#define MAXPV 35.0f

// ---------------- scratch (static device globals; no allocation) ----------------
__device__ __align__(16) float g_accum[BATCH*7*G3];   // [b][ch][voxel] ch: 0..2 sum xyz, 3 count, 4..6 sum rgb
__device__ unsigned g_minmax[BATCH*6];                // [b][0..2]=min enc, [b][3..5]=max enc
__device__ float g_A1t[7*64];                         // fused layer1 weights, [k][j]
__device__ float g_c1[64];
__device__ __align__(16) float g_A2[64*128];          // fused layer2 weights, [k][c]
__device__ float g_c2[128];

// ---------------- helpers ----------------
__device__ __forceinline__ unsigned fenc(float f){
    unsigned u = __float_as_uint(f);
    return (u & 0x80000000u) ? ~u : (u | 0x80000000u);
}
__device__ __forceinline__ float fdec(unsigned u){
    return (u & 0x80000000u) ? __uint_as_float(u ^ 0x80000000u) : __uint_as_float(~u);
}
__device__ __forceinline__ unsigned long long pk2(float lo, float hi){
    unsigned long long r;
    asm("mov.b64 %0, {%1, %2};" : "=l"(r) : "f"(lo), "f"(hi));
    return r;
}
__device__ __forceinline__ void upk2(unsigned long long v, float& lo, float& hi){
    asm("mov.b64 {%0, %1}, %2;" : "=f"(lo), "=f"(hi) : "l"(v));
}
// packed f32x2 FMA: 2x fp32 FMA throughput on sm_103a (ptxas never emits this from C++)
__device__ __forceinline__ void ffma2(unsigned long long& acc, unsigned long long x, unsigned long long y){
    asm("fma.rn.f32x2 %0, %1, %2, %0;" : "+l"(acc) : "l"(x), "l"(y));
}

// ---------------- kernel 1: zero accumulators + init min/max ----------------
__global__ void k_init(){
    int i = blockIdx.x*blockDim.x + threadIdx.x;
    const int total = BATCH*7*G3/4;      // float4 count = 1,835,008
    if(i < total) ((float4*)g_accum)[i] = make_float4(0.f,0.f,0.f,0.f);
    if(i < BATCH*6) g_minmax[i] = ((i % 6) < 3) ? 0xFFFFFFFFu : 0u;
}

// ---------------- kernel 2: fuse Linear+BN into A,c ----------------
__global__ void k_fuse(const float* __restrict__ W1, const float* __restrict__ b1,
                       const float* __restrict__ g1, const float* __restrict__ be1,
                       const float* __restrict__ rm1, const float* __restrict__ rv1,
                       const float* __restrict__ W2, const float* __restrict__ b2,
                       const float* __restrict__ g2, const float* __restrict__ be2,
                       const float* __restrict__ rm2, const float* __restrict__ rv2){
    int t = threadIdx.x;
    if(t < 64){
        float s = g1[t] / sqrtf(rv1[t] + 1e-5f);
        g_c1[t] = (b1[t] - rm1[t]) * s + be1[t];
        #pragma unroll
        for(int k = 0; k < 7; k++) g_A1t[k*64 + t] = W1[t*7 + k] * s;
    }
    if(t < 128){
        float s = g2[t] / sqrtf(rv2[t] + 1e-5f);
        g_c2[t] = (b2[t] - rm2[t]) * s + be2[t];
        for(int k = 0; k < 64; k++) g_A2[k*128 + t] = W2[t*64 + k] * s;
    }
}

// ---------------- kernel 3: per-batch coordinate min/max ----------------
__global__ void k_minmax(const float* __restrict__ pc){
    int b = blockIdx.y;
    const float* px = pc + b*6*NPTS;
    float mn0= 3.4e38f, mn1= 3.4e38f, mn2= 3.4e38f;
    float mx0=-3.4e38f, mx1=-3.4e38f, mx2=-3.4e38f;
    for(int n = blockIdx.x*blockDim.x + threadIdx.x; n < NPTS; n += gridDim.x*blockDim.x){
        float x = px[n], y = px[NPTS+n], z = px[2*NPTS+n];
        mn0 = fminf(mn0,x); mx0 = fmaxf(mx0,x);
        mn1 = fminf(mn1,y); mx1 = fmaxf(mx1,y);
        mn2 = fminf(mn2,z); mx2 = fmaxf(mx2,z);
    }
    #pragma unroll
    for(int s = 16; s; s >>= 1){
        mn0 = fminf(mn0, __shfl_xor_sync(~0u, mn0, s));
        mn1 = fminf(mn1, __shfl_xor_sync(~0u, mn1, s));
        mn2 = fminf(mn2, __shfl_xor_sync(~0u, mn2, s));
        mx0 = fmaxf(mx0, __shfl_xor_sync(~0u, mx0, s));
        mx1 = fmaxf(mx1, __shfl_xor_sync(~0u, mx1, s));
        mx2 = fmaxf(mx2, __shfl_xor_sync(~0u, mx2, s));
    }
    if((threadIdx.x & 31) == 0){
        atomicMin(&g_minmax[b*6+0], fenc(mn0));
        atomicMin(&g_minmax[b*6+1], fenc(mn1));
        atomicMin(&g_minmax[b*6+2], fenc(mn2));
        atomicMax(&g_minmax[b*6+3], fenc(mx0));
        atomicMax(&g_minmax[b*6+4], fenc(mx1));
        atomicMax(&g_minmax[b*6+5], fenc(mx2));
    }
}

// ---------------- kernel 4: voxel scatter ----------------
__global__ void k_voxel(const float* __restrict__ pc){
    int b = blockIdx.y;
    const float* p = pc + b*6*NPTS;
    float mn0 = fdec(g_minmax[b*6+0]);
    float mn1 = fdec(g_minmax[b*6+1]);
    float mn2 = fdec(g_minmax[b*6+2]);
    float d0 = fdec(g_minmax[b*6+3]) - mn0 + 1e-7f;
    float d1 = fdec(g_minmax[b*6+4]) - mn1 + 1e-7f;
    float d2 = fdec(g_minmax[b*6+5]) - mn2 + 1e-7f;
    float* acc = g_accum + b*7*G3;
    for(int n = blockIdx.x*blockDim.x + threadIdx.x; n < NPTS; n += gridDim.x*blockDim.x){
        float x = p[n], y = p[NPTS+n], z = p[2*NPTS+n];
        float r = p[3*NPTS+n], g = p[4*NPTS+n], bl = p[5*NPTS+n];
        // replicate reference rounding exactly: ((c-min)/(max-min+1e-7)) * 63, clip [0, 62.9999]
        float tx = __fmul_rn(__fdiv_rn(x - mn0, d0), 63.0f);
        float ty = __fmul_rn(__fdiv_rn(y - mn1, d1), 63.0f);
        float tz = __fmul_rn(__fdiv_rn(z - mn2, d2), 63.0f);
        tx = fminf(fmaxf(tx, 0.0f), 62.9999f);
        ty = fminf(fmaxf(ty, 0.0f), 62.9999f);
        tz = fminf(fmaxf(tz, 0.0f), 62.9999f);
        int flat = (((int)tx)*GDIM + (int)ty)*GDIM + (int)tz;
        atomicAdd(acc +        flat, x);
        atomicAdd(acc +   G3 + flat, y);
        atomicAdd(acc + 2*G3 + flat, z);
        atomicAdd(acc + 3*G3 + flat, 1.0f);
        atomicAdd(acc + 4*G3 + flat, r);
        atomicAdd(acc + 5*G3 + flat, g);
        atomicAdd(acc + 6*G3 + flat, bl);
    }
}

// ---------------- kernel 5: fused MLP over 128-voxel tiles ----------------
// smem (floats): A2S[8192] | hS[128*68] | featS[128*8] | A1tS[512] | c1S[64] | c2S[128] | occS[128]
#define SM_A2   0
#define SM_H    8192
#define SM_FEAT 16896
#define SM_A1   17920
#define SM_C1   18432
#define SM_C2   18496
#define SM_OCC  18624
#define SM_FLOATS 18752   // 75008 bytes

__global__ void __launch_bounds__(256, 2) k_mlp(float* __restrict__ out){
    extern __shared__ float sm[];
    float* A2S   = sm + SM_A2;
    float* hS    = sm + SM_H;
    float* featS = sm + SM_FEAT;
    float* A1tS  = sm + SM_A1;
    float* c1S   = sm + SM_C1;
    float* c2S   = sm + SM_C2;
    float* occS  = sm + SM_OCC;

    int tid   = threadIdx.x;
    int b     = blockIdx.x >> 11;          // 2048 tiles per batch
    int tile  = blockIdx.x & 2047;
    int vbase = tile << 7;                 // 128 voxels per tile
    const float* acc = g_accum + b*7*G3 + vbase;

    float cnt = 0.f;
    if(tid < 128) cnt = acc[3*G3 + tid];
    int any = __syncthreads_or(tid < 128 && cnt > 0.f);

    float* ob = out + (size_t)b*128*G3 + vbase;
    if(!any){
        // empty tile: write 128 channels x 128 voxels of zeros, coalesced float4
        float4 z = make_float4(0.f,0.f,0.f,0.f);
        for(int i = tid; i < 4096; i += 256){
            int c = i >> 5, q = i & 31;
            ((float4*)(ob + (size_t)c*G3))[q] = z;
        }
        return;
    }

    if(tid < 128){
        float dn = fmaxf(cnt, 1.0f);
        float sx = acc[tid],      sy = acc[G3+tid],   sz = acc[2*G3+tid];
        float sr = acc[4*G3+tid], sg = acc[5*G3+tid], sb = acc[6*G3+tid];
        featS[tid*8+0] = __fdiv_rn(sx, dn);
        featS[tid*8+1] = __fdiv_rn(sy, dn);
        featS[tid*8+2] = __fdiv_rn(sz, dn);
        featS[tid*8+3] = __fdiv_rn(fminf(cnt, MAXPV), MAXPV);
        featS[tid*8+4] = __fdiv_rn(sr, dn);
        featS[tid*8+5] = __fdiv_rn(sg, dn);
        featS[tid*8+6] = __fdiv_rn(sb, dn);
        featS[tid*8+7] = 0.f;
        occS[tid] = (cnt > 0.f) ? 1.0f : 0.0f;
    }
    for(int i = tid; i < 448;  i += 256) A1tS[i] = g_A1t[i];
    if(tid < 64)  c1S[tid] = g_c1[tid];
    if(tid < 128) c2S[tid] = g_c2[tid];
    for(int i = tid; i < 8192; i += 256) A2S[i]  = g_A2[i];
    __syncthreads();

    // layer 1: h[v][j] = relu(feat[v] . A1[:,j] + c1[j]); 128*64 outputs
    for(int i = tid; i < 8192; i += 256){
        int v = i >> 6, j = i & 63;
        float s = c1S[j];
        const float* f = featS + v*8;
        #pragma unroll
        for(int k = 0; k < 7; k++) s = fmaf(f[k], A1tS[k*64+j], s);
        hS[v*68 + j] = fmaxf(s, 0.f);
    }
    __syncthreads();

    // layer 2: 8 voxels x 8 channels per thread, packed f32x2 FMA
    int cg = tid & 15, vg = tid >> 4;
    int c0 = cg*8, v0 = vg*8;
    unsigned long long a[8][4];
    #pragma unroll
    for(int vi = 0; vi < 8; vi++)
        #pragma unroll
        for(int p = 0; p < 4; p++) a[vi][p] = 0ull;

    const float* hb = hS + v0*68;
    for(int k0 = 0; k0 < 64; k0 += 4){
        float4 hv[8];
        #pragma unroll
        for(int vi = 0; vi < 8; vi++) hv[vi] = *(const float4*)(hb + vi*68 + k0);
        #pragma unroll
        for(int kk = 0; kk < 4; kk++){
            float4 wA = *(const float4*)(A2S + (k0+kk)*128 + c0);
            float4 wB = *(const float4*)(A2S + (k0+kk)*128 + c0 + 4);
            unsigned long long w0 = pk2(wA.x, wA.y), w1 = pk2(wA.z, wA.w);
            unsigned long long w2 = pk2(wB.x, wB.y), w3 = pk2(wB.z, wB.w);
            #pragma unroll
            for(int vi = 0; vi < 8; vi++){
                float h = ((const float*)&hv[vi])[kk];
                unsigned long long hh = pk2(h, h);
                ffma2(a[vi][0], hh, w0);
                ffma2(a[vi][1], hh, w1);
                ffma2(a[vi][2], hh, w2);
                ffma2(a[vi][3], hh, w3);
            }
        }
    }

    // epilogue: +c2, relu, occupancy mask, transpose to [channel][voxel] float4 stores
    float o[8][8];   // [channel_local][vi]
    #pragma unroll
    for(int vi = 0; vi < 8; vi++){
        float oc = occS[v0 + vi];
        #pragma unroll
        for(int p = 0; p < 4; p++){
            float lo, hi;
            upk2(a[vi][p], lo, hi);
            o[2*p  ][vi] = fmaxf(lo + c2S[c0+2*p  ], 0.f) * oc;
            o[2*p+1][vi] = fmaxf(hi + c2S[c0+2*p+1], 0.f) * oc;
        }
    }
    #pragma unroll
    for(int cl = 0; cl < 8; cl++){
        float* dst = ob + (size_t)(c0+cl)*G3 + v0;
        *(float4*)(dst)     = make_float4(o[cl][0], o[cl][1], o[cl][2], o[cl][3]);
        *(float4*)(dst + 4) = make_float4(o[cl][4], o[cl][5], o[cl][6], o[cl][7]);
    }
}

// ---------------- launch ----------------
extern "C" void kernel_launch(void* const* d_in, const int* in_sizes, int n_in,
                              void* d_out, int out_size){
    const float* pc  = (const float*)d_in[0];
    const float* W1  = (const float*)d_in[1];
    const float* b1  = (const float*)d_in[2];
    const float* g1  = (const float*)d_in[3];
    const float* be1 = (const float*)d_in[4];
    const float* rm1 = (const float*)d_in[5];
    const float* rv1 = (const float*)d_in[6];
    const float* W2  = (const float*)d_in[7];
    const float* b2  = (const float*)d_in[8];
    const float* g2  = (const float*)d_in[9];
    const float* be2 = (const float*)d_in[10];
    const float* rm2 = (const float*)d_in[11];
    const float* rv2 = (const float*)d_in[12];

    cudaFuncSetAttribute(k_mlp, cudaFuncAttributeMaxDynamicSharedMemorySize, SM_FLOATS*4);

    k_init<<<7168, 256>>>();
    k_fuse<<<1, 128>>>(W1,b1,g1,be1,rm1,rv1,W2,b2,g2,be2,rm2,rv2);
    k_minmax<<<dim3(64,4), 256>>>(pc);
    k_voxel<<<dim3(782,4), 256>>>(pc);
    k_mlp<<<BATCH*2048, 256, SM_FLOATS*4>>>((float*)d_out);
}

// round 3
// speedup vs baseline: 1.0546x; 1.0546x over previous
#include <cuda_runtime.h>
#include <cstdint>
#include <cstddef>

typedef unsigned long long ull;

#define GDIM 64
#define G3 (GDIM*GDIM*GDIM)
#define BATCH 4
#define NPTS 200000
#define MAXPV 35.0f

// ---------------- scratch (static device globals; no allocation) ----------------
// accumulator interleaved per voxel: [b][voxel][8] = {sx,sy,sz,count, sr,sg,sb,pad}
__device__ __align__(16) float g_accum[BATCH*G3*8];
__device__ unsigned g_minmax[BATCH*6];                // [b][0..2]=min enc, [b][3..5]=max enc
__device__ float g_A1t[7*64];                         // fused layer1 weights, [k][j]
__device__ float g_c1[64];
__device__ __align__(16) float g_A2[64*128];          // fused layer2 weights, [k][c]
__device__ float g_c2[128];

// ---------------- helpers ----------------
__device__ __forceinline__ unsigned fenc(float f){
    unsigned u = __float_as_uint(f);
    return (u & 0x80000000u) ? ~u : (u | 0x80000000u);
}
__device__ __forceinline__ float fdec(unsigned u){
    return (u & 0x80000000u) ? __uint_as_float(u ^ 0x80000000u) : __uint_as_float(~u);
}
__device__ __forceinline__ void upk2(ull v, float& lo, float& hi){
    asm("mov.b64 {%0, %1}, %2;" : "=f"(lo), "=f"(hi) : "l"(v));
}
// packed f32x2 FMA: 2x fp32 FMA throughput on sm_103a
__device__ __forceinline__ void ffma2(ull& acc, ull x, ull y){
    asm("fma.rn.f32x2 %0, %1, %2, %0;" : "+l"(acc) : "l"(x), "l"(y));
}
// 16B shared load straight into two b64 operand pairs (no pack MOVs)
__device__ __forceinline__ void lds2x64(ull& a, ull& b, unsigned addr){
    asm volatile("ld.shared.v2.b64 {%0, %1}, [%2];" : "=l"(a), "=l"(b) : "r"(addr));
}
// vector global reduction: one op covers 4 floats in one sector
__device__ __forceinline__ void red4(float* addr, float x, float y, float z, float w){
    asm volatile("red.global.add.v4.f32 [%0], {%1,%2,%3,%4};"
                 :: "l"(addr), "f"(x), "f"(y), "f"(z), "f"(w) : "memory");
}

// ---------------- kernel 1: zero accumulators + init min/max ----------------
__global__ void k_init(){
    int i = blockIdx.x*blockDim.x + threadIdx.x;
    const int total = BATCH*G3*8/4;      // 2,097,152 float4
    if(i < total) ((float4*)g_accum)[i] = make_float4(0.f,0.f,0.f,0.f);
    if(i < BATCH*6) g_minmax[i] = ((i % 6) < 3) ? 0xFFFFFFFFu : 0u;
}

// ---------------- kernel 2: fuse Linear+BN into A,c ----------------
__global__ void k_fuse(const float* __restrict__ W1, const float* __restrict__ b1,
                       const float* __restrict__ g1, const float* __restrict__ be1,
                       const float* __restrict__ rm1, const float* __restrict__ rv1,
                       const float* __restrict__ W2, const float* __restrict__ b2,
                       const float* __restrict__ g2, const float* __restrict__ be2,
                       const float* __restrict__ rm2, const float* __restrict__ rv2){
    int t = threadIdx.x;
    if(t < 64){
        float s = g1[t] / sqrtf(rv1[t] + 1e-5f);
        g_c1[t] = (b1[t] - rm1[t]) * s + be1[t];
        #pragma unroll
        for(int k = 0; k < 7; k++) g_A1t[k*64 + t] = W1[t*7 + k] * s;
    }
    if(t < 128){
        float s = g2[t] / sqrtf(rv2[t] + 1e-5f);
        g_c2[t] = (b2[t] - rm2[t]) * s + be2[t];
        for(int k = 0; k < 64; k++) g_A2[k*128 + t] = W2[t*64 + k] * s;
    }
}

// ---------------- kernel 3: per-batch coordinate min/max ----------------
__global__ void k_minmax(const float* __restrict__ pc){
    int b = blockIdx.y;
    const float* px = pc + b*6*NPTS;
    float mn0= 3.4e38f, mn1= 3.4e38f, mn2= 3.4e38f;
    float mx0=-3.4e38f, mx1=-3.4e38f, mx2=-3.4e38f;
    for(int n = blockIdx.x*blockDim.x + threadIdx.x; n < NPTS; n += gridDim.x*blockDim.x){
        float x = px[n], y = px[NPTS+n], z = px[2*NPTS+n];
        mn0 = fminf(mn0,x); mx0 = fmaxf(mx0,x);
        mn1 = fminf(mn1,y); mx1 = fmaxf(mx1,y);
        mn2 = fminf(mn2,z); mx2 = fmaxf(mx2,z);
    }
    #pragma unroll
    for(int s = 16; s; s >>= 1){
        mn0 = fminf(mn0, __shfl_xor_sync(~0u, mn0, s));
        mn1 = fminf(mn1, __shfl_xor_sync(~0u, mn1, s));
        mn2 = fminf(mn2, __shfl_xor_sync(~0u, mn2, s));
        mx0 = fmaxf(mx0, __shfl_xor_sync(~0u, mx0, s));
        mx1 = fmaxf(mx1, __shfl_xor_sync(~0u, mx1, s));
        mx2 = fmaxf(mx2, __shfl_xor_sync(~0u, mx2, s));
    }
    if((threadIdx.x & 31) == 0){
        atomicMin(&g_minmax[b*6+0], fenc(mn0));
        atomicMin(&g_minmax[b*6+1], fenc(mn1));
        atomicMin(&g_minmax[b*6+2], fenc(mn2));
        atomicMax(&g_minmax[b*6+3], fenc(mx0));
        atomicMax(&g_minmax[b*6+4], fenc(mx1));
        atomicMax(&g_minmax[b*6+5], fenc(mx2));
    }
}

// ---------------- kernel 4: voxel scatter (2 vector REDs per point) ----------------
__global__ void k_voxel(const float* __restrict__ pc){
    int b = blockIdx.y;
    const float* p = pc + b*6*NPTS;
    float mn0 = fdec(g_minmax[b*6+0]);
    float mn1 = fdec(g_minmax[b*6+1]);
    float mn2 = fdec(g_minmax[b*6+2]);
    float d0 = fdec(g_minmax[b*6+3]) - mn0 + 1e-7f;
    float d1 = fdec(g_minmax[b*6+4]) - mn1 + 1e-7f;
    float d2 = fdec(g_minmax[b*6+5]) - mn2 + 1e-7f;
    float* acc = g_accum + (size_t)b*G3*8;
    for(int n = blockIdx.x*blockDim.x + threadIdx.x; n < NPTS; n += gridDim.x*blockDim.x){
        float x = p[n], y = p[NPTS+n], z = p[2*NPTS+n];
        float r = p[3*NPTS+n], g = p[4*NPTS+n], bl = p[5*NPTS+n];
        // replicate reference rounding exactly
        float tx = __fmul_rn(__fdiv_rn(x - mn0, d0), 63.0f);
        float ty = __fmul_rn(__fdiv_rn(y - mn1, d1), 63.0f);
        float tz = __fmul_rn(__fdiv_rn(z - mn2, d2), 63.0f);
        tx = fminf(fmaxf(tx, 0.0f), 62.9999f);
        ty = fminf(fmaxf(ty, 0.0f), 62.9999f);
        tz = fminf(fmaxf(tz, 0.0f), 62.9999f);
        int flat = (((int)tx)*GDIM + (int)ty)*GDIM + (int)tz;
        float* v = acc + (size_t)flat*8;
        red4(v,     x, y, z, 1.0f);
        red4(v + 4, r, g, bl, 0.0f);
    }
}

// ---------------- kernel 5: fused MLP over 128-voxel tiles ----------------
// smem floats: A2S[8192] | hS2[128*64*2] | featS[1024] | A1tS[512] | c1S[64] | c2S[128] | occS[128] | occ8S[16]
#define SM_A2    0
#define SM_H     8192
#define SM_FEAT  24576
#define SM_A1    25600
#define SM_C1    26112
#define SM_C2    26176
#define SM_OCC   26304
#define SM_OCC8  26432
#define SM_FLOATS 26464   // 105856 bytes

__global__ void __launch_bounds__(256, 2) k_mlp(float* __restrict__ out){
    extern __shared__ float sm[];
    float* A2S   = sm + SM_A2;
    float* featS = sm + SM_FEAT;
    float* A1tS  = sm + SM_A1;
    float* c1S   = sm + SM_C1;
    float* c2S   = sm + SM_C2;
    float* occS  = sm + SM_OCC;
    float* occ8S = sm + SM_OCC8;

    int tid   = threadIdx.x;
    int b     = blockIdx.x >> 11;          // 2048 tiles per batch
    int tile  = blockIdx.x & 2047;
    int vbase = tile << 7;                 // 128 voxels per tile
    const float* acc = g_accum + ((size_t)b*G3 + vbase)*8;

    float cnt = 0.f;
    if(tid < 128) cnt = acc[tid*8 + 3];
    int any = __syncthreads_or(tid < 128 && cnt > 0.f);

    float* ob = out + (size_t)b*128*G3 + vbase;
    if(!any){
        float4 z = make_float4(0.f,0.f,0.f,0.f);
        for(int i = tid; i < 4096; i += 256){
            int c = i >> 5, q = i & 31;
            ((float4*)(ob + (size_t)c*G3))[q] = z;
        }
        return;
    }

    if(tid < 128){
        float4 p0 = *(const float4*)(acc + tid*8);
        float4 p1 = *(const float4*)(acc + tid*8 + 4);
        float dn = fmaxf(p0.w, 1.0f);
        featS[tid*8+0] = __fdiv_rn(p0.x, dn);
        featS[tid*8+1] = __fdiv_rn(p0.y, dn);
        featS[tid*8+2] = __fdiv_rn(p0.z, dn);
        featS[tid*8+3] = __fdiv_rn(fminf(p0.w, MAXPV), MAXPV);
        featS[tid*8+4] = __fdiv_rn(p1.x, dn);
        featS[tid*8+5] = __fdiv_rn(p1.y, dn);
        featS[tid*8+6] = __fdiv_rn(p1.z, dn);
        featS[tid*8+7] = 0.f;
        occS[tid] = (p0.w > 0.f) ? 1.0f : 0.0f;
    }
    for(int i = tid; i < 448;  i += 256) A1tS[i] = g_A1t[i];
    if(tid < 64)  c1S[tid] = g_c1[tid];
    if(tid < 128) c2S[tid] = g_c2[tid];
    for(int i = tid; i < 2048; i += 256) ((float4*)A2S)[i] = ((const float4*)g_A2)[i];
    __syncthreads();

    if(tid < 16){
        float s = 0.f;
        #pragma unroll
        for(int i = 0; i < 8; i++) s += occS[tid*8 + i];
        occ8S[tid] = s;
    }
    __syncthreads();

    // layer 1: only occupied 8-voxel groups; store h pre-duplicated as float2{h,h}
    float2* hS2 = (float2*)(sm + SM_H);
    for(int i = tid; i < 8192; i += 256){
        int v = i >> 6, j = i & 63;
        if(occ8S[v >> 3] > 0.f){
            float s = c1S[j];
            const float* f = featS + v*8;
            #pragma unroll
            for(int k = 0; k < 7; k++) s = fmaf(f[k], A1tS[k*64+j], s);
            float h = fmaxf(s, 0.f);
            hS2[v*64 + j] = make_float2(h, h);
        }
    }
    __syncthreads();

    // layer 2: 8 voxels x 8 channels per thread, pure FFMA2 + v2.b64 shared loads
    int cg = tid & 15, vg = tid >> 4;
    int c0 = cg*8, v0 = vg*8;
    unsigned smemBase = (unsigned)__cvta_generic_to_shared(sm);
    unsigned hAddr = smemBase + SM_H*4 + (unsigned)v0*64*8;
    unsigned aAddr = smemBase + SM_A2*4 + (unsigned)c0*4;

    if(occ8S[vg] > 0.f){
        ull a[8][4];
        #pragma unroll
        for(int vi = 0; vi < 8; vi++)
            #pragma unroll
            for(int p = 0; p < 4; p++) a[vi][p] = 0ull;

        #pragma unroll 4
        for(int k = 0; k < 64; k += 2){
            // weight row k: channels c0..c0+7 occupy 32 bytes at byte offset c0*4;
            // split as two 16B v2.b64 loads at +0 and +16. Next k-row is +512.
            ull w00,w01,w02,w03, w10,w11,w12,w13;
            lds2x64(w00, w01, aAddr + (unsigned)k*512);
            lds2x64(w02, w03, aAddr + (unsigned)k*512 + 16);
            lds2x64(w10, w11, aAddr + (unsigned)k*512 + 512);
            lds2x64(w12, w13, aAddr + (unsigned)k*512 + 528);
            #pragma unroll
            for(int vi = 0; vi < 8; vi++){
                ull h0, h1;
                lds2x64(h0, h1, hAddr + (unsigned)vi*512 + (unsigned)k*8);
                ffma2(a[vi][0], h0, w00);
                ffma2(a[vi][1], h0, w01);
                ffma2(a[vi][2], h0, w02);
                ffma2(a[vi][3], h0, w03);
                ffma2(a[vi][0], h1, w10);
                ffma2(a[vi][1], h1, w11);
                ffma2(a[vi][2], h1, w12);
                ffma2(a[vi][3], h1, w13);
            }
        }

        // epilogue in two vi-halves to limit register pressure
        #pragma unroll
        for(int half = 0; half < 2; half++){
            float o[8][4];
            #pragma unroll
            for(int vi = 0; vi < 4; vi++){
                int viG = half*4 + vi;
                float oc = occS[v0 + viG];
                #pragma unroll
                for(int p = 0; p < 4; p++){
                    float lo, hi;
                    upk2(a[viG][p], lo, hi);
                    o[2*p  ][vi] = fmaxf(lo + c2S[c0+2*p  ], 0.f) * oc;
                    o[2*p+1][vi] = fmaxf(hi + c2S[c0+2*p+1], 0.f) * oc;
                }
            }
            #pragma unroll
            for(int cl = 0; cl < 8; cl++){
                float* dst = ob + (size_t)(c0+cl)*G3 + v0 + half*4;
                *(float4*)dst = make_float4(o[cl][0], o[cl][1], o[cl][2], o[cl][3]);
            }
        }
    } else {
        float4 z = make_float4(0.f,0.f,0.f,0.f);
        #pragma unroll
        for(int cl = 0; cl < 8; cl++){
            float* dst = ob + (size_t)(c0+cl)*G3 + v0;
            *(float4*)(dst)     = z;
            *(float4*)(dst + 4) = z;
        }
    }
}

// ---------------- launch ----------------
extern "C" void kernel_launch(void* const* d_in, const int* in_sizes, int n_in,
                              void* d_out, int out_size){
    const float* pc  = (const float*)d_in[0];
    const float* W1  = (const float*)d_in[1];
    const float* b1  = (const float*)d_in[2];
    const float* g1  = (const float*)d_in[3];
    const float* be1 = (const float*)d_in[4];
    const float* rm1 = (const float*)d_in[5];
    const float* rv1 = (const float*)d_in[6];
    const float* W2  = (const float*)d_in[7];
    const float* b2  = (const float*)d_in[8];
    const float* g2  = (const float*)d_in[9];
    const float* be2 = (const float*)d_in[10];
    const float* rm2 = (const float*)d_in[11];
    const float* rv2 = (const float*)d_in[12];

    cudaFuncSetAttribute(k_mlp, cudaFuncAttributeMaxDynamicSharedMemorySize, SM_FLOATS*4);

    k_init<<<8192, 256>>>();
    k_fuse<<<1, 128>>>(W1,b1,g1,be1,rm1,rv1,W2,b2,g2,be2,rm2,rv2);
    k_minmax<<<dim3(64,4), 256>>>(pc);
    k_voxel<<<dim3(782,4), 256>>>(pc);
    k_mlp<<<BATCH*2048, 256, SM_FLOATS*4>>>((float*)d_out);
}

// round 4
// speedup vs baseline: 1.1129x; 1.0552x over previous
#include <cuda_runtime.h>
#include <cstdint>
#include <cstddef>

typedef unsigned long long ull;

#define GDIM 64
#define G3 (GDIM*GDIM*GDIM)
#define BATCH 4
#define NPTS 200000
#define MAXPV 35.0f

// ---------------- scratch (static device globals; no allocation) ----------------
// accumulator interleaved per voxel: [b][voxel][8] = {sx,sy,sz,count, sr,sg,sb,pad}
__device__ __align__(16) float g_accum[BATCH*G3*8];
__device__ unsigned g_minmax[BATCH*6];                // [b][0..2]=min enc, [b][3..5]=max enc
__device__ float g_A1t[7*64];                         // fused layer1 weights, [k][j]
__device__ float g_c1[64];
__device__ __align__(16) float g_A2[64*128];          // fused layer2 weights, [k][c]
__device__ float g_c2[128];

// ---------------- helpers ----------------
__device__ __forceinline__ unsigned fenc(float f){
    unsigned u = __float_as_uint(f);
    return (u & 0x80000000u) ? ~u : (u | 0x80000000u);
}
__device__ __forceinline__ float fdec(unsigned u){
    return (u & 0x80000000u) ? __uint_as_float(u ^ 0x80000000u) : __uint_as_float(~u);
}
__device__ __forceinline__ void upk2(ull v, float& lo, float& hi){
    asm("mov.b64 {%0, %1}, %2;" : "=f"(lo), "=f"(hi) : "l"(v));
}
// packed f32x2 FMA
__device__ __forceinline__ void ffma2(ull& acc, ull x, ull y){
    asm("fma.rn.f32x2 %0, %1, %2, %0;" : "+l"(acc) : "l"(x), "l"(y));
}
// 16B shared load straight into two b64 operand pairs
__device__ __forceinline__ void lds2x64(ull& a, ull& b, unsigned addr){
    asm volatile("ld.shared.v2.b64 {%0, %1}, [%2];" : "=l"(a), "=l"(b) : "r"(addr));
}
// vector global reduction: one op covers 4 floats in one sector
__device__ __forceinline__ void red4(float* addr, float x, float y, float z, float w){
    asm volatile("red.global.add.v4.f32 [%0], {%1,%2,%3,%4};"
                 :: "l"(addr), "f"(x), "f"(y), "f"(z), "f"(w) : "memory");
}

// ---------------- kernel 1: zero accumulators + init min/max ----------------
__global__ void k_init(){
    int i = blockIdx.x*blockDim.x + threadIdx.x;
    const int total = BATCH*G3*8/4;
    if(i < total) ((float4*)g_accum)[i] = make_float4(0.f,0.f,0.f,0.f);
    if(i < BATCH*6) g_minmax[i] = ((i % 6) < 3) ? 0xFFFFFFFFu : 0u;
}

// ---------------- kernel 2: fuse Linear+BN into A,c ----------------
__global__ void k_fuse(const float* __restrict__ W1, const float* __restrict__ b1,
                       const float* __restrict__ g1, const float* __restrict__ be1,
                       const float* __restrict__ rm1, const float* __restrict__ rv1,
                       const float* __restrict__ W2, const float* __restrict__ b2,
                       const float* __restrict__ g2, const float* __restrict__ be2,
                       const float* __restrict__ rm2, const float* __restrict__ rv2){
    int t = threadIdx.x;
    if(t < 64){
        float s = g1[t] / sqrtf(rv1[t] + 1e-5f);
        g_c1[t] = (b1[t] - rm1[t]) * s + be1[t];
        #pragma unroll
        for(int k = 0; k < 7; k++) g_A1t[k*64 + t] = W1[t*7 + k] * s;
    }
    if(t < 128){
        float s = g2[t] / sqrtf(rv2[t] + 1e-5f);
        g_c2[t] = (b2[t] - rm2[t]) * s + be2[t];
        for(int k = 0; k < 64; k++) g_A2[k*128 + t] = W2[t*64 + k] * s;
    }
}

// ---------------- kernel 3: per-batch coordinate min/max ----------------
__global__ void k_minmax(const float* __restrict__ pc){
    int b = blockIdx.y;
    const float* px = pc + b*6*NPTS;
    float mn0= 3.4e38f, mn1= 3.4e38f, mn2= 3.4e38f;
    float mx0=-3.4e38f, mx1=-3.4e38f, mx2=-3.4e38f;
    for(int n = blockIdx.x*blockDim.x + threadIdx.x; n < NPTS; n += gridDim.x*blockDim.x){
        float x = px[n], y = px[NPTS+n], z = px[2*NPTS+n];
        mn0 = fminf(mn0,x); mx0 = fmaxf(mx0,x);
        mn1 = fminf(mn1,y); mx1 = fmaxf(mx1,y);
        mn2 = fminf(mn2,z); mx2 = fmaxf(mx2,z);
    }
    #pragma unroll
    for(int s = 16; s; s >>= 1){
        mn0 = fminf(mn0, __shfl_xor_sync(~0u, mn0, s));
        mn1 = fminf(mn1, __shfl_xor_sync(~0u, mn1, s));
        mn2 = fminf(mn2, __shfl_xor_sync(~0u, mn2, s));
        mx0 = fmaxf(mx0, __shfl_xor_sync(~0u, mx0, s));
        mx1 = fmaxf(mx1, __shfl_xor_sync(~0u, mx1, s));
        mx2 = fmaxf(mx2, __shfl_xor_sync(~0u, mx2, s));
    }
    if((threadIdx.x & 31) == 0){
        atomicMin(&g_minmax[b*6+0], fenc(mn0));
        atomicMin(&g_minmax[b*6+1], fenc(mn1));
        atomicMin(&g_minmax[b*6+2], fenc(mn2));
        atomicMax(&g_minmax[b*6+3], fenc(mx0));
        atomicMax(&g_minmax[b*6+4], fenc(mx1));
        atomicMax(&g_minmax[b*6+5], fenc(mx2));
    }
}

// ---------------- kernel 4: voxel scatter (2 vector REDs per point) ----------------
__global__ void k_voxel(const float* __restrict__ pc){
    int b = blockIdx.y;
    const float* p = pc + b*6*NPTS;
    float mn0 = fdec(g_minmax[b*6+0]);
    float mn1 = fdec(g_minmax[b*6+1]);
    float mn2 = fdec(g_minmax[b*6+2]);
    float d0 = fdec(g_minmax[b*6+3]) - mn0 + 1e-7f;
    float d1 = fdec(g_minmax[b*6+4]) - mn1 + 1e-7f;
    float d2 = fdec(g_minmax[b*6+5]) - mn2 + 1e-7f;
    float* acc = g_accum + (size_t)b*G3*8;
    for(int n = blockIdx.x*blockDim.x + threadIdx.x; n < NPTS; n += gridDim.x*blockDim.x){
        float x = p[n], y = p[NPTS+n], z = p[2*NPTS+n];
        float r = p[3*NPTS+n], g = p[4*NPTS+n], bl = p[5*NPTS+n];
        float tx = __fmul_rn(__fdiv_rn(x - mn0, d0), 63.0f);
        float ty = __fmul_rn(__fdiv_rn(y - mn1, d1), 63.0f);
        float tz = __fmul_rn(__fdiv_rn(z - mn2, d2), 63.0f);
        tx = fminf(fmaxf(tx, 0.0f), 62.9999f);
        ty = fminf(fmaxf(ty, 0.0f), 62.9999f);
        tz = fminf(fmaxf(tz, 0.0f), 62.9999f);
        int flat = (((int)tx)*GDIM + (int)ty)*GDIM + (int)tz;
        float* v = acc + (size_t)flat*8;
        red4(v,     x, y, z, 1.0f);
        red4(v + 4, r, g, bl, 0.0f);
    }
}

// ---------------- kernel 5: fused MLP over 128-voxel tiles ----------------
// smem floats: A2S[8192] | hS2/oS[16384] | featS[1024] | A1tS[512] | c1S[64] | c2S[128] | occS[128] | occ8S[16]
#define SM_A2    0
#define SM_H     8192
#define SM_FEAT  24576
#define SM_A1    25600
#define SM_C1    26112
#define SM_C2    26176
#define SM_OCC   26304
#define SM_OCC8  26432
#define SM_FLOATS 26464   // 105856 bytes

__global__ void __launch_bounds__(256, 2) k_mlp(float* __restrict__ out){
    extern __shared__ float sm[];
    float* A2S   = sm + SM_A2;
    float* featS = sm + SM_FEAT;
    float* A1tS  = sm + SM_A1;
    float* c1S   = sm + SM_C1;
    float* c2S   = sm + SM_C2;
    float* occS  = sm + SM_OCC;
    float* occ8S = sm + SM_OCC8;

    int tid   = threadIdx.x;
    int b     = blockIdx.x >> 11;          // 2048 tiles per batch
    int tile  = blockIdx.x & 2047;
    int vbase = tile << 7;                 // 128 voxels per tile
    const float* acc = g_accum + ((size_t)b*G3 + vbase)*8;

    float cnt = 0.f;
    if(tid < 128) cnt = acc[tid*8 + 3];
    int any = __syncthreads_or(tid < 128 && cnt > 0.f);

    float* ob = out + (size_t)b*128*G3 + vbase;
    if(!any){
        float4 z = make_float4(0.f,0.f,0.f,0.f);
        for(int i = tid; i < 4096; i += 256){
            int c = i >> 5, q = i & 31;
            ((float4*)(ob + (size_t)c*G3))[q] = z;
        }
        return;
    }

    if(tid < 128){
        float4 p0 = *(const float4*)(acc + tid*8);
        float4 p1 = *(const float4*)(acc + tid*8 + 4);
        float dn = fmaxf(p0.w, 1.0f);
        featS[tid*8+0] = __fdiv_rn(p0.x, dn);
        featS[tid*8+1] = __fdiv_rn(p0.y, dn);
        featS[tid*8+2] = __fdiv_rn(p0.z, dn);
        featS[tid*8+3] = __fdiv_rn(fminf(p0.w, MAXPV), MAXPV);
        featS[tid*8+4] = __fdiv_rn(p1.x, dn);
        featS[tid*8+5] = __fdiv_rn(p1.y, dn);
        featS[tid*8+6] = __fdiv_rn(p1.z, dn);
        featS[tid*8+7] = 0.f;
        occS[tid] = (p0.w > 0.f) ? 1.0f : 0.0f;
    }
    for(int i = tid; i < 448;  i += 256) A1tS[i] = g_A1t[i];
    if(tid < 64)  c1S[tid] = g_c1[tid];
    if(tid < 128) c2S[tid] = g_c2[tid];
    for(int i = tid; i < 2048; i += 256) ((float4*)A2S)[i] = ((const float4*)g_A2)[i];
    __syncthreads();

    if(tid < 16){
        float s = 0.f;
        #pragma unroll
        for(int i = 0; i < 8; i++) s += occS[tid*8 + i];
        occ8S[tid] = s;
    }
    __syncthreads();

    // layer 1: only occupied 8-voxel groups; store h pre-duplicated as float2{h,h}
    float2* hS2 = (float2*)(sm + SM_H);
    for(int i = tid; i < 8192; i += 256){
        int v = i >> 6, j = i & 63;
        if(occ8S[v >> 3] > 0.f){
            float s = c1S[j];
            const float* f = featS + v*8;
            #pragma unroll
            for(int k = 0; k < 7; k++) s = fmaf(f[k], A1tS[k*64+j], s);
            float h = fmaxf(s, 0.f);
            hS2[v*64 + j] = make_float2(h, h);
        }
    }
    __syncthreads();

    // layer 2: 8 voxels x 8 channels per thread, FFMA2 + v2.b64 shared loads
    int cg = tid & 15, vg = tid >> 4;
    int c0 = cg*8, v0 = vg*8;
    unsigned smemBase = (unsigned)__cvta_generic_to_shared(sm);
    unsigned hAddr = smemBase + SM_H*4 + (unsigned)v0*64*8;
    unsigned aAddr = smemBase + SM_A2*4 + (unsigned)c0*4;

    ull a[8][4];
    #pragma unroll
    for(int vi = 0; vi < 8; vi++)
        #pragma unroll
        for(int p = 0; p < 4; p++) a[vi][p] = 0ull;

    if(occ8S[vg] > 0.f){
        #pragma unroll 4
        for(int k = 0; k < 64; k += 2){
            ull w00,w01,w02,w03, w10,w11,w12,w13;
            lds2x64(w00, w01, aAddr + (unsigned)k*512);
            lds2x64(w02, w03, aAddr + (unsigned)k*512 + 16);
            lds2x64(w10, w11, aAddr + (unsigned)k*512 + 512);
            lds2x64(w12, w13, aAddr + (unsigned)k*512 + 528);
            #pragma unroll
            for(int vi = 0; vi < 8; vi++){
                ull h0, h1;
                lds2x64(h0, h1, hAddr + (unsigned)vi*512 + (unsigned)k*8);
                ffma2(a[vi][0], h0, w00);
                ffma2(a[vi][1], h0, w01);
                ffma2(a[vi][2], h0, w02);
                ffma2(a[vi][3], h0, w03);
                ffma2(a[vi][0], h1, w10);
                ffma2(a[vi][1], h1, w11);
                ffma2(a[vi][2], h1, w12);
                ffma2(a[vi][3], h1, w13);
            }
        }
    }

    // read occupancy BEFORE oS overwrites smem regions is fine (occS separate region)
    float occv[8];
    #pragma unroll
    for(int vi = 0; vi < 8; vi++) occv[vi] = occS[v0 + vi];

    __syncthreads();   // all warps done reading hS2 / A2S

    // epilogue: write tile into smem oS[c][v] (chunk-XOR swizzled), then coalesced stores.
    // swizzle: physical 16B chunk = vq ^ (c>>3). For this thread c>>3 == cg.
    float* oS = sm + SM_H;   // 128 x 128 floats = 64KB
    #pragma unroll
    for(int cl = 0; cl < 8; cl++){
        int c = c0 + cl;
        int p = cl >> 1;
        float bias = c2S[c];
        #pragma unroll
        for(int half = 0; half < 2; half++){
            float vvals[4];
            #pragma unroll
            for(int j = 0; j < 4; j++){
                int vi = half*4 + j;
                float lo, hi;
                upk2(a[vi][p], lo, hi);
                float t = (cl & 1) ? hi : lo;
                vvals[j] = fmaxf(t + bias, 0.f) * occv[vi];
            }
            int q  = 2*vg + half;          // logical 16B chunk index (0..31)
            int pc = q ^ cg;               // swizzled physical chunk
            *(float4*)(oS + c*128 + pc*4) = make_float4(vvals[0], vvals[1], vvals[2], vvals[3]);
        }
    }
    __syncthreads();

    // coalesced store phase: warp handles one channel row at a time
    for(int i = tid; i < 4096; i += 256){
        int c = i >> 5, vq = i & 31;
        int s = (c >> 3) & 15;
        float4 v = *(const float4*)(oS + c*128 + ((vq ^ s) << 2));
        ((float4*)(ob + (size_t)c*G3))[vq] = v;
    }
}

// ---------------- launch ----------------
extern "C" void kernel_launch(void* const* d_in, const int* in_sizes, int n_in,
                              void* d_out, int out_size){
    const float* pc  = (const float*)d_in[0];
    const float* W1  = (const float*)d_in[1];
    const float* b1  = (const float*)d_in[2];
    const float* g1  = (const float*)d_in[3];
    const float* be1 = (const float*)d_in[4];
    const float* rm1 = (const float*)d_in[5];
    const float* rv1 = (const float*)d_in[6];
    const float* W2  = (const float*)d_in[7];
    const float* b2  = (const float*)d_in[8];
    const float* g2  = (const float*)d_in[9];
    const float* be2 = (const float*)d_in[10];
    const float* rm2 = (const float*)d_in[11];
    const float* rv2 = (const float*)d_in[12];

    cudaFuncSetAttribute(k_mlp, cudaFuncAttributeMaxDynamicSharedMemorySize, SM_FLOATS*4);

    k_init<<<8192, 256>>>();
    k_fuse<<<1, 128>>>(W1,b1,g1,be1,rm1,rv1,W2,b2,g2,be2,rm2,rv2);
    k_minmax<<<dim3(64,4), 256>>>(pc);
    k_voxel<<<dim3(782,4), 256>>>(pc);
    k_mlp<<<BATCH*2048, 256, SM_FLOATS*4>>>((float*)d_out);
}

// round 5
// speedup vs baseline: 1.1825x; 1.0625x over previous
#include <cuda_runtime.h>
#include <cstdint>
#include <cstddef>

typedef unsigned long long ull;

#define GDIM 64
#define G3 (GDIM*GDIM*GDIM)
#define BATCH 4
#define NPTS 200000
#define MAXPV 35.0f

// ---------------- scratch ----------------
__device__ __align__(16) float g_accum[BATCH*G3*8];   // [b][voxel][8] = {sx,sy,sz,cnt, sr,sg,sb,pad}
__device__ unsigned g_minmax[BATCH*6];
__device__ float g_A1t[7*64];
__device__ float g_c1[64];
__device__ __align__(16) float g_A2[64*128];
__device__ float g_c2[128];

// ---------------- helpers ----------------
__device__ __forceinline__ unsigned fenc(float f){
    unsigned u = __float_as_uint(f);
    return (u & 0x80000000u) ? ~u : (u | 0x80000000u);
}
__device__ __forceinline__ float fdec(unsigned u){
    return (u & 0x80000000u) ? __uint_as_float(u ^ 0x80000000u) : __uint_as_float(~u);
}
__device__ __forceinline__ void upk2(ull v, float& lo, float& hi){
    asm("mov.b64 {%0, %1}, %2;" : "=f"(lo), "=f"(hi) : "l"(v));
}
__device__ __forceinline__ void ffma2(ull& acc, ull x, ull y){
    asm("fma.rn.f32x2 %0, %1, %2, %0;" : "+l"(acc) : "l"(x), "l"(y));
}
__device__ __forceinline__ void lds2x64(ull& a, ull& b, unsigned addr){
    asm volatile("ld.shared.v2.b64 {%0, %1}, [%2];" : "=l"(a), "=l"(b) : "r"(addr));
}
__device__ __forceinline__ void red4(float* addr, float x, float y, float z, float w){
    asm volatile("red.global.add.v4.f32 [%0], {%1,%2,%3,%4};"
                 :: "l"(addr), "f"(x), "f"(y), "f"(z), "f"(w) : "memory");
}

// ---------------- kernel 1 ----------------
__global__ void k_init(){
    int i = blockIdx.x*blockDim.x + threadIdx.x;
    const int total = BATCH*G3*8/4;
    if(i < total) ((float4*)g_accum)[i] = make_float4(0.f,0.f,0.f,0.f);
    if(i < BATCH*6) g_minmax[i] = ((i % 6) < 3) ? 0xFFFFFFFFu : 0u;
}

// ---------------- kernel 2 ----------------
__global__ void k_fuse(const float* __restrict__ W1, const float* __restrict__ b1,
                       const float* __restrict__ g1, const float* __restrict__ be1,
                       const float* __restrict__ rm1, const float* __restrict__ rv1,
                       const float* __restrict__ W2, const float* __restrict__ b2,
                       const float* __restrict__ g2, const float* __restrict__ be2,
                       const float* __restrict__ rm2, const float* __restrict__ rv2){
    int t = threadIdx.x;
    if(t < 64){
        float s = g1[t] / sqrtf(rv1[t] + 1e-5f);
        g_c1[t] = (b1[t] - rm1[t]) * s + be1[t];
        #pragma unroll
        for(int k = 0; k < 7; k++) g_A1t[k*64 + t] = W1[t*7 + k] * s;
    }
    if(t < 128){
        float s = g2[t] / sqrtf(rv2[t] + 1e-5f);
        g_c2[t] = (b2[t] - rm2[t]) * s + be2[t];
        for(int k = 0; k < 64; k++) g_A2[k*128 + t] = W2[t*64 + k] * s;
    }
}

// ---------------- kernel 3 ----------------
__global__ void k_minmax(const float* __restrict__ pc){
    int b = blockIdx.y;
    const float* px = pc + b*6*NPTS;
    float mn0= 3.4e38f, mn1= 3.4e38f, mn2= 3.4e38f;
    float mx0=-3.4e38f, mx1=-3.4e38f, mx2=-3.4e38f;
    for(int n = blockIdx.x*blockDim.x + threadIdx.x; n < NPTS; n += gridDim.x*blockDim.x){
        float x = px[n], y = px[NPTS+n], z = px[2*NPTS+n];
        mn0 = fminf(mn0,x); mx0 = fmaxf(mx0,x);
        mn1 = fminf(mn1,y); mx1 = fmaxf(mx1,y);
        mn2 = fminf(mn2,z); mx2 = fmaxf(mx2,z);
    }
    #pragma unroll
    for(int s = 16; s; s >>= 1){
        mn0 = fminf(mn0, __shfl_xor_sync(~0u, mn0, s));
        mn1 = fminf(mn1, __shfl_xor_sync(~0u, mn1, s));
        mn2 = fminf(mn2, __shfl_xor_sync(~0u, mn2, s));
        mx0 = fmaxf(mx0, __shfl_xor_sync(~0u, mx0, s));
        mx1 = fmaxf(mx1, __shfl_xor_sync(~0u, mx1, s));
        mx2 = fmaxf(mx2, __shfl_xor_sync(~0u, mx2, s));
    }
    if((threadIdx.x & 31) == 0){
        atomicMin(&g_minmax[b*6+0], fenc(mn0));
        atomicMin(&g_minmax[b*6+1], fenc(mn1));
        atomicMin(&g_minmax[b*6+2], fenc(mn2));
        atomicMax(&g_minmax[b*6+3], fenc(mx0));
        atomicMax(&g_minmax[b*6+4], fenc(mx1));
        atomicMax(&g_minmax[b*6+5], fenc(mx2));
    }
}

// ---------------- kernel 4 ----------------
__global__ void k_voxel(const float* __restrict__ pc){
    int b = blockIdx.y;
    const float* p = pc + b*6*NPTS;
    float mn0 = fdec(g_minmax[b*6+0]);
    float mn1 = fdec(g_minmax[b*6+1]);
    float mn2 = fdec(g_minmax[b*6+2]);
    float d0 = fdec(g_minmax[b*6+3]) - mn0 + 1e-7f;
    float d1 = fdec(g_minmax[b*6+4]) - mn1 + 1e-7f;
    float d2 = fdec(g_minmax[b*6+5]) - mn2 + 1e-7f;
    float* acc = g_accum + (size_t)b*G3*8;
    for(int n = blockIdx.x*blockDim.x + threadIdx.x; n < NPTS; n += gridDim.x*blockDim.x){
        float x = p[n], y = p[NPTS+n], z = p[2*NPTS+n];
        float r = p[3*NPTS+n], g = p[4*NPTS+n], bl = p[5*NPTS+n];
        float tx = __fmul_rn(__fdiv_rn(x - mn0, d0), 63.0f);
        float ty = __fmul_rn(__fdiv_rn(y - mn1, d1), 63.0f);
        float tz = __fmul_rn(__fdiv_rn(z - mn2, d2), 63.0f);
        tx = fminf(fmaxf(tx, 0.0f), 62.9999f);
        ty = fminf(fmaxf(ty, 0.0f), 62.9999f);
        tz = fminf(fmaxf(tz, 0.0f), 62.9999f);
        int flat = (((int)tx)*GDIM + (int)ty)*GDIM + (int)tz;
        float* v = acc + (size_t)flat*8;
        red4(v,     x, y, z, 1.0f);
        red4(v + 4, r, g, bl, 0.0f);
    }
}

// ---------------- kernel 5: fused MLP with voxel compaction ----------------
// smem floats: A2S[8192] | hS2/oS[16384] | featS[1024] | A1tS[512] | c1S[64] | c2S[128] | perm[128] | aux[12]
#define SM_A2    0
#define SM_H     8192
#define SM_FEAT  24576
#define SM_A1    25600
#define SM_C1    26112
#define SM_C2    26176
#define SM_PERM  26304
#define SM_AUX   26432
#define SM_FLOATS 26448   // 105792 bytes

template<int NC>
__device__ __forceinline__ void l2_body(unsigned aAddr, unsigned hAddr, ull (&a)[8][4]){
    #pragma unroll 4
    for(int k = 0; k < 64; k += 2){
        ull w00,w01,w02,w03, w10,w11,w12,w13;
        lds2x64(w00, w01, aAddr + (unsigned)k*512);
        lds2x64(w02, w03, aAddr + (unsigned)k*512 + 16);
        lds2x64(w10, w11, aAddr + (unsigned)k*512 + 512);
        lds2x64(w12, w13, aAddr + (unsigned)k*512 + 528);
        #pragma unroll
        for(int ch = 0; ch < NC; ch++){
            ull h0, h1;
            lds2x64(h0, h1, hAddr + (unsigned)ch*8192 + (unsigned)k*8);
            ffma2(a[ch][0], h0, w00);
            ffma2(a[ch][1], h0, w01);
            ffma2(a[ch][2], h0, w02);
            ffma2(a[ch][3], h0, w03);
            ffma2(a[ch][0], h1, w10);
            ffma2(a[ch][1], h1, w11);
            ffma2(a[ch][2], h1, w12);
            ffma2(a[ch][3], h1, w13);
        }
    }
}

__global__ void __launch_bounds__(256, 2) k_mlp(float* __restrict__ out){
    extern __shared__ float sm[];
    float* A2S   = sm + SM_A2;
    float* featS = sm + SM_FEAT;
    float* A1tS  = sm + SM_A1;
    float* c1S   = sm + SM_C1;
    float* c2S   = sm + SM_C2;
    int*   permS = (int*)(sm + SM_PERM);
    int*   auxS  = (int*)(sm + SM_AUX);   // [0..3] warp counts, [4..7] offsets, [8] M

    int tid   = threadIdx.x;
    int b     = blockIdx.x >> 11;
    int tile  = blockIdx.x & 2047;
    int vbase = tile << 7;
    const float* acc = g_accum + ((size_t)b*G3 + vbase)*8;

    float cnt = 0.f;
    if(tid < 128) cnt = acc[tid*8 + 3];
    int occ = (tid < 128) && (cnt > 0.f);
    int any = __syncthreads_or(occ);

    float* ob = out + (size_t)b*128*G3 + vbase;
    if(!any){
        float4 z = make_float4(0.f,0.f,0.f,0.f);
        for(int i = tid; i < 4096; i += 256){
            int c = i >> 5, q = i & 31;
            ((float4*)(ob + (size_t)c*G3))[q] = z;
        }
        return;
    }

    // phase 1: features + ballot compaction bookkeeping + weight loads
    if(tid < 128){
        float4 p0 = *(const float4*)(acc + tid*8);
        float4 p1 = *(const float4*)(acc + tid*8 + 4);
        float dn = fmaxf(p0.w, 1.0f);
        featS[tid*8+0] = __fdiv_rn(p0.x, dn);
        featS[tid*8+1] = __fdiv_rn(p0.y, dn);
        featS[tid*8+2] = __fdiv_rn(p0.z, dn);
        featS[tid*8+3] = __fdiv_rn(fminf(p0.w, MAXPV), MAXPV);
        featS[tid*8+4] = __fdiv_rn(p1.x, dn);
        featS[tid*8+5] = __fdiv_rn(p1.y, dn);
        featS[tid*8+6] = __fdiv_rn(p1.z, dn);
        featS[tid*8+7] = 0.f;
    }
    unsigned bal = __ballot_sync(0xFFFFFFFFu, occ);
    if(tid < 128 && (tid & 31) == 0) auxS[tid >> 5] = __popc(bal);

    for(int i = tid; i < 448;  i += 256) A1tS[i] = g_A1t[i];
    if(tid < 64)  c1S[tid] = g_c1[tid];
    if(tid < 128) c2S[tid] = g_c2[tid];
    for(int i = tid; i < 2048; i += 256) ((float4*)A2S)[i] = ((const float4*)g_A2)[i];
    __syncthreads();

    if(tid == 0){
        int s = 0;
        #pragma unroll
        for(int w = 0; w < 4; w++){ auxS[4+w] = s; s += auxS[w]; }
        auxS[8] = s;
    }
    __syncthreads();
    if(occ){
        int pos = auxS[4 + (tid >> 5)] + __popc(bal & ((1u << (tid & 31)) - 1u));
        permS[pos] = tid;
    }
    __syncthreads();

    int M = auxS[8];
    int nchunk = (M + 15) >> 4;          // 1..8
    int Mp = nchunk << 4;

    // phase 2: layer 1 for compacted slots (padded slots -> h = 0)
    float2* hS2 = (float2*)(sm + SM_H);
    for(int i = tid; i < Mp*64; i += 256){
        int slot = i >> 6, j = i & 63;
        float h = 0.f;
        if(slot < M){
            int v = permS[slot];
            float s = c1S[j];
            const float* f = featS + v*8;
            #pragma unroll
            for(int k = 0; k < 7; k++) s = fmaf(f[k], A1tS[k*64+j], s);
            h = fmaxf(s, 0.f);
        }
        hS2[slot*64 + j] = make_float2(h, h);
    }
    __syncthreads();

    // phase 3: layer 2, template-dispatched on chunk count
    int cg = tid & 15, vg = tid >> 4;
    int c0 = cg*8;
    unsigned smemBase = (unsigned)__cvta_generic_to_shared(sm);
    unsigned hAddr = smemBase + SM_H*4 + (unsigned)vg*512;
    unsigned aAddr = smemBase + SM_A2*4 + (unsigned)c0*4;

    ull a[8][4];
    #pragma unroll
    for(int ch = 0; ch < 8; ch++)
        #pragma unroll
        for(int p = 0; p < 4; p++) a[ch][p] = 0ull;

    switch(nchunk){
        case 1: l2_body<1>(aAddr, hAddr, a); break;
        case 2: l2_body<2>(aAddr, hAddr, a); break;
        case 3: l2_body<3>(aAddr, hAddr, a); break;
        case 4: l2_body<4>(aAddr, hAddr, a); break;
        case 5: l2_body<5>(aAddr, hAddr, a); break;
        case 6: l2_body<6>(aAddr, hAddr, a); break;
        case 7: l2_body<7>(aAddr, hAddr, a); break;
        default: l2_body<8>(aAddr, hAddr, a); break;
    }
    __syncthreads();   // hS2 reads done everywhere

    // phase 4: zero output tile in smem, scatter computed voxels, coalesced store
    float* oS = sm + SM_H;
    float4 z4 = make_float4(0.f,0.f,0.f,0.f);
    for(int i = tid; i < 4096; i += 256) ((float4*)oS)[i] = z4;
    __syncthreads();

    #pragma unroll
    for(int ch = 0; ch < 8; ch++){
        if(ch < nchunk){
            int slot = ch*16 + vg;
            if(slot < M){
                int v = permS[slot];
                int base = (((v >> 2) ^ cg) << 2) + (v & 3);
                #pragma unroll
                for(int p = 0; p < 4; p++){
                    float lo, hi;
                    upk2(a[ch][p], lo, hi);
                    oS[(c0+2*p  )*128 + base] = fmaxf(lo + c2S[c0+2*p  ], 0.f);
                    oS[(c0+2*p+1)*128 + base] = fmaxf(hi + c2S[c0+2*p+1], 0.f);
                }
            }
        }
    }
    __syncthreads();

    for(int i = tid; i < 4096; i += 256){
        int c = i >> 5, vq = i & 31;
        int s = (c >> 3) & 15;
        float4 v = *(const float4*)(oS + c*128 + ((vq ^ s) << 2));
        ((float4*)(ob + (size_t)c*G3))[vq] = v;
    }
}

// ---------------- launch ----------------
extern "C" void kernel_launch(void* const* d_in, const int* in_sizes, int n_in,
                              void* d_out, int out_size){
    const float* pc  = (const float*)d_in[0];
    const float* W1  = (const float*)d_in[1];
    const float* b1  = (const float*)d_in[2];
    const float* g1  = (const float*)d_in[3];
    const float* be1 = (const float*)d_in[4];
    const float* rm1 = (const float*)d_in[5];
    const float* rv1 = (const float*)d_in[6];
    const float* W2  = (const float*)d_in[7];
    const float* b2  = (const float*)d_in[8];
    const float* g2  = (const float*)d_in[9];
    const float* be2 = (const float*)d_in[10];
    const float* rm2 = (const float*)d_in[11];
    const float* rv2 = (const float*)d_in[12];

    cudaFuncSetAttribute(k_mlp, cudaFuncAttributeMaxDynamicSharedMemorySize, SM_FLOATS*4);

    k_init<<<8192, 256>>>();
    k_fuse<<<1, 128>>>(W1,b1,g1,be1,rm1,rv1,W2,b2,g2,be2,rm2,rv2);
    k_minmax<<<dim3(64,4), 256>>>(pc);
    k_voxel<<<dim3(782,4), 256>>>(pc);
    k_mlp<<<BATCH*2048, 256, SM_FLOATS*4>>>((float*)d_out);
}

// round 6
// speedup vs baseline: 1.3156x; 1.1125x over previous
#include <cuda_runtime.h>
#include <cstdint>
#include <cstddef>

typedef unsigned long long ull;

#define GDIM 64
#define G3 (GDIM*GDIM*GDIM)
#define BATCH 4
#define NPTS 200000
#define MAXPV 35.0f
#define NTILES 8192

// ---------------- scratch ----------------
__device__ __align__(16) float g_accum[BATCH*G3*8];   // [b][voxel][8] = {sx,sy,sz,cnt, sr,sg,sb,pad}
__device__ unsigned g_minmax[BATCH*6];
__device__ float g_A1t[7*64];
__device__ float g_c1[64];
__device__ __align__(16) float g_A2[64*128];
__device__ float g_c2[128];
__device__ unsigned g_work;

// ---------------- helpers ----------------
__device__ __forceinline__ unsigned fenc(float f){
    unsigned u = __float_as_uint(f);
    return (u & 0x80000000u) ? ~u : (u | 0x80000000u);
}
__device__ __forceinline__ float fdec(unsigned u){
    return (u & 0x80000000u) ? __uint_as_float(u ^ 0x80000000u) : __uint_as_float(~u);
}
__device__ __forceinline__ void upk2(ull v, float& lo, float& hi){
    asm("mov.b64 {%0, %1}, %2;" : "=f"(lo), "=f"(hi) : "l"(v));
}
__device__ __forceinline__ void ffma2(ull& acc, ull x, ull y){
    asm("fma.rn.f32x2 %0, %1, %2, %0;" : "+l"(acc) : "l"(x), "l"(y));
}
__device__ __forceinline__ void lds2x64(ull& a, ull& b, unsigned addr){
    asm volatile("ld.shared.v2.b64 {%0, %1}, [%2];" : "=l"(a), "=l"(b) : "r"(addr));
}
__device__ __forceinline__ void red4(float* addr, float x, float y, float z, float w){
    asm volatile("red.global.add.v4.f32 [%0], {%1,%2,%3,%4};"
                 :: "l"(addr), "f"(x), "f"(y), "f"(z), "f"(w) : "memory");
}

// ---------------- kernel 1: prep (zero accum + fuse weights + init minmax/work) ----------------
__global__ void k_prep(const float* __restrict__ W1, const float* __restrict__ b1,
                       const float* __restrict__ g1, const float* __restrict__ be1,
                       const float* __restrict__ rm1, const float* __restrict__ rv1,
                       const float* __restrict__ W2, const float* __restrict__ b2,
                       const float* __restrict__ g2, const float* __restrict__ be2,
                       const float* __restrict__ rm2, const float* __restrict__ rv2){
    int i = blockIdx.x*blockDim.x + threadIdx.x;   // grid 8192*256 = exactly accum float4 count
    ((float4*)g_accum)[i] = make_float4(0.f,0.f,0.f,0.f);
    if(blockIdx.x == 0){
        int t = threadIdx.x;
        if(t < BATCH*6) g_minmax[t] = ((t % 6) < 3) ? 0xFFFFFFFFu : 0u;
        if(t == 0) g_work = 0u;
        if(t < 64){
            float s = g1[t] / sqrtf(rv1[t] + 1e-5f);
            g_c1[t] = (b1[t] - rm1[t]) * s + be1[t];
            #pragma unroll
            for(int k = 0; k < 7; k++) g_A1t[k*64 + t] = W1[t*7 + k] * s;
        }
        if(t < 128){
            float s = g2[t] / sqrtf(rv2[t] + 1e-5f);
            g_c2[t] = (b2[t] - rm2[t]) * s + be2[t];
            for(int k = 0; k < 64; k++) g_A2[k*128 + t] = W2[t*64 + k] * s;
        }
    }
}

// ---------------- kernel 2: per-batch coordinate min/max ----------------
__global__ void k_minmax(const float* __restrict__ pc){
    int b = blockIdx.y;
    const float* px = pc + b*6*NPTS;
    float mn0= 3.4e38f, mn1= 3.4e38f, mn2= 3.4e38f;
    float mx0=-3.4e38f, mx1=-3.4e38f, mx2=-3.4e38f;
    for(int n = blockIdx.x*blockDim.x + threadIdx.x; n < NPTS; n += gridDim.x*blockDim.x){
        float x = px[n], y = px[NPTS+n], z = px[2*NPTS+n];
        mn0 = fminf(mn0,x); mx0 = fmaxf(mx0,x);
        mn1 = fminf(mn1,y); mx1 = fmaxf(mx1,y);
        mn2 = fminf(mn2,z); mx2 = fmaxf(mx2,z);
    }
    #pragma unroll
    for(int s = 16; s; s >>= 1){
        mn0 = fminf(mn0, __shfl_xor_sync(~0u, mn0, s));
        mn1 = fminf(mn1, __shfl_xor_sync(~0u, mn1, s));
        mn2 = fminf(mn2, __shfl_xor_sync(~0u, mn2, s));
        mx0 = fmaxf(mx0, __shfl_xor_sync(~0u, mx0, s));
        mx1 = fmaxf(mx1, __shfl_xor_sync(~0u, mx1, s));
        mx2 = fmaxf(mx2, __shfl_xor_sync(~0u, mx2, s));
    }
    if((threadIdx.x & 31) == 0){
        atomicMin(&g_minmax[b*6+0], fenc(mn0));
        atomicMin(&g_minmax[b*6+1], fenc(mn1));
        atomicMin(&g_minmax[b*6+2], fenc(mn2));
        atomicMax(&g_minmax[b*6+3], fenc(mx0));
        atomicMax(&g_minmax[b*6+4], fenc(mx1));
        atomicMax(&g_minmax[b*6+5], fenc(mx2));
    }
}

// ---------------- kernel 3: voxel scatter ----------------
__global__ void k_voxel(const float* __restrict__ pc){
    int b = blockIdx.y;
    const float* p = pc + b*6*NPTS;
    float mn0 = fdec(g_minmax[b*6+0]);
    float mn1 = fdec(g_minmax[b*6+1]);
    float mn2 = fdec(g_minmax[b*6+2]);
    float d0 = fdec(g_minmax[b*6+3]) - mn0 + 1e-7f;
    float d1 = fdec(g_minmax[b*6+4]) - mn1 + 1e-7f;
    float d2 = fdec(g_minmax[b*6+5]) - mn2 + 1e-7f;
    float* acc = g_accum + (size_t)b*G3*8;
    for(int n = blockIdx.x*blockDim.x + threadIdx.x; n < NPTS; n += gridDim.x*blockDim.x){
        float x = p[n], y = p[NPTS+n], z = p[2*NPTS+n];
        float r = p[3*NPTS+n], g = p[4*NPTS+n], bl = p[5*NPTS+n];
        float tx = __fmul_rn(__fdiv_rn(x - mn0, d0), 63.0f);
        float ty = __fmul_rn(__fdiv_rn(y - mn1, d1), 63.0f);
        float tz = __fmul_rn(__fdiv_rn(z - mn2, d2), 63.0f);
        tx = fminf(fmaxf(tx, 0.0f), 62.9999f);
        ty = fminf(fmaxf(ty, 0.0f), 62.9999f);
        tz = fminf(fmaxf(tz, 0.0f), 62.9999f);
        int flat = (((int)tx)*GDIM + (int)ty)*GDIM + (int)tz;
        float* v = acc + (size_t)flat*8;
        red4(v,     x, y, z, 1.0f);
        red4(v + 4, r, g, bl, 0.0f);
    }
}

// ---------------- kernel 4: persistent fused MLP ----------------
#define SM_A2    0
#define SM_H     8192
#define SM_FEAT  24576
#define SM_A1    25600
#define SM_C1    26112
#define SM_C2    26176
#define SM_PERM  26304
#define SM_AUX   26432
#define SM_FLOATS 26448   // 105792 bytes

template<int NC>
__device__ __forceinline__ void l2_body(unsigned aAddr, unsigned hAddr, ull (&a)[8][4]){
    #pragma unroll 4
    for(int k = 0; k < 64; k += 2){
        ull w00,w01,w02,w03, w10,w11,w12,w13;
        lds2x64(w00, w01, aAddr + (unsigned)k*512);
        lds2x64(w02, w03, aAddr + (unsigned)k*512 + 16);
        lds2x64(w10, w11, aAddr + (unsigned)k*512 + 512);
        lds2x64(w12, w13, aAddr + (unsigned)k*512 + 528);
        #pragma unroll
        for(int ch = 0; ch < NC; ch++){
            ull h0, h1;
            lds2x64(h0, h1, hAddr + (unsigned)ch*8192 + (unsigned)k*8);
            ffma2(a[ch][0], h0, w00);
            ffma2(a[ch][1], h0, w01);
            ffma2(a[ch][2], h0, w02);
            ffma2(a[ch][3], h0, w03);
            ffma2(a[ch][0], h1, w10);
            ffma2(a[ch][1], h1, w11);
            ffma2(a[ch][2], h1, w12);
            ffma2(a[ch][3], h1, w13);
        }
    }
}

__global__ void __launch_bounds__(256, 2) k_mlp(float* __restrict__ out){
    extern __shared__ float sm[];
    float* A2S   = sm + SM_A2;
    float* featS = sm + SM_FEAT;
    float* A1tS  = sm + SM_A1;
    float* c1S   = sm + SM_C1;
    float* c2S   = sm + SM_C2;
    int*   permS = (int*)(sm + SM_PERM);
    volatile int* auxS = (volatile int*)(sm + SM_AUX);   // [0..3] warp popc, [9] next tile id

    int tid = threadIdx.x;
    int cg = tid & 15, vg = tid >> 4;
    int c0 = cg*8;
    unsigned smemBase = (unsigned)__cvta_generic_to_shared(sm);
    unsigned hAddr = smemBase + SM_H*4 + (unsigned)vg*512;
    unsigned aAddr = smemBase + SM_A2*4 + (unsigned)c0*4;
    float* oS = sm + SM_H;

    // ---- prologue: load weights once per block ----
    for(int i = tid; i < 448;  i += 256) A1tS[i] = g_A1t[i];
    if(tid < 64)  c1S[tid] = g_c1[tid];
    if(tid < 128) c2S[tid] = g_c2[tid];
    for(int i = tid; i < 2048; i += 256) ((float4*)A2S)[i] = ((const float4*)g_A2)[i];
    if(tid == 0) auxS[9] = (int)atomicAdd(&g_work, 1u);
    __syncthreads();
    int t = auxS[9];
    __syncthreads();

    float4 p0 = make_float4(0,0,0,0), p1 = make_float4(0,0,0,0);
    if(tid < 128 && t < NTILES){
        const float* acc = g_accum + ((size_t)(t >> 11)*G3 + ((t & 2047) << 7))*8;
        p0 = *(const float4*)(acc + tid*8);
        p1 = *(const float4*)(acc + tid*8 + 4);
    }

    while(t < NTILES){
        if(tid == 0) auxS[9] = (int)atomicAdd(&g_work, 1u);

        int occ = (tid < 128) && (p0.w > 0.f);
        unsigned bal = __ballot_sync(0xFFFFFFFFu, occ);
        if(tid < 128 && (tid & 31) == 0) auxS[tid >> 5] = __popc(bal);
        if(occ){
            float dn = fmaxf(p0.w, 1.0f);
            featS[tid*8+0] = __fdiv_rn(p0.x, dn);
            featS[tid*8+1] = __fdiv_rn(p0.y, dn);
            featS[tid*8+2] = __fdiv_rn(p0.z, dn);
            featS[tid*8+3] = __fdiv_rn(fminf(p0.w, MAXPV), MAXPV);
            featS[tid*8+4] = __fdiv_rn(p1.x, dn);
            featS[tid*8+5] = __fdiv_rn(p1.y, dn);
            featS[tid*8+6] = __fdiv_rn(p1.z, dn);
            featS[tid*8+7] = 0.f;
        }
        __syncthreads();                     // (1) auxS[9], counts, featS published

        int tn = auxS[9];
        // prefetch next tile's accumulator rows (hidden behind compute below)
        float4 q0 = make_float4(0,0,0,0), q1 = make_float4(0,0,0,0);
        if(tid < 128 && tn < NTILES){
            const float* accn = g_accum + ((size_t)(tn >> 11)*G3 + ((tn & 2047) << 7))*8;
            q0 = *(const float4*)(accn + tid*8);
            q1 = *(const float4*)(accn + tid*8 + 4);
        }

        int n0 = auxS[0], n1 = auxS[1], n2 = auxS[2], n3 = auxS[3];
        int M = n0 + n1 + n2 + n3;
        float* ob = out + (size_t)(t >> 11)*128*G3 + ((t & 2047) << 7);

        if(M == 0){
            float4 z = make_float4(0.f,0.f,0.f,0.f);
            for(int i = tid; i < 4096; i += 256){
                int c = i >> 5, q = i & 31;
                ((float4*)(ob + (size_t)c*G3))[q] = z;
            }
            t = tn; p0 = q0; p1 = q1;
            __syncthreads();                 // (2e) protect auxS rewrite next iter
            continue;
        }

        if(occ){
            int w = tid >> 5;
            int off = (w > 0 ? n0 : 0) + (w > 1 ? n1 : 0) + (w > 2 ? n2 : 0);
            permS[off + __popc(bal & ((1u << (tid & 31)) - 1u))] = tid;
        }
        __syncthreads();                     // (2) perm ready

        int nchunk = (M + 15) >> 4;
        int Mp = nchunk << 4;

        // layer 1 on compacted slots (padded -> 0)
        float2* hS2 = (float2*)oS;
        for(int i = tid; i < Mp*64; i += 256){
            int slot = i >> 6, j = i & 63;
            float h = 0.f;
            if(slot < M){
                int v = permS[slot];
                float s = c1S[j];
                const float* f = featS + v*8;
                #pragma unroll
                for(int k = 0; k < 7; k++) s = fmaf(f[k], A1tS[k*64+j], s);
                h = fmaxf(s, 0.f);
            }
            hS2[slot*64 + j] = make_float2(h, h);
        }
        __syncthreads();                     // (3) h ready

        ull a[8][4];
        #pragma unroll
        for(int ch = 0; ch < 8; ch++)
            #pragma unroll
            for(int p = 0; p < 4; p++) a[ch][p] = 0ull;

        switch(nchunk){
            case 1: l2_body<1>(aAddr, hAddr, a); break;
            case 2: l2_body<2>(aAddr, hAddr, a); break;
            case 3: l2_body<3>(aAddr, hAddr, a); break;
            case 4: l2_body<4>(aAddr, hAddr, a); break;
            case 5: l2_body<5>(aAddr, hAddr, a); break;
            case 6: l2_body<6>(aAddr, hAddr, a); break;
            case 7: l2_body<7>(aAddr, hAddr, a); break;
            default: l2_body<8>(aAddr, hAddr, a); break;
        }
        __syncthreads();                     // (4) h reads done -> oS reuse ok

        float4 z4 = make_float4(0.f,0.f,0.f,0.f);
        for(int i = tid; i < 4096; i += 256) ((float4*)oS)[i] = z4;
        __syncthreads();                     // (5) oS zeroed

        #pragma unroll
        for(int ch = 0; ch < 8; ch++){
            if(ch < nchunk){
                int slot = ch*16 + vg;
                if(slot < M){
                    int v = permS[slot];
                    int base = (((v >> 2) ^ cg) << 2) + (v & 3);
                    #pragma unroll
                    for(int p = 0; p < 4; p++){
                        float lo, hi;
                        upk2(a[ch][p], lo, hi);
                        oS[(c0+2*p  )*128 + base] = fmaxf(lo + c2S[c0+2*p  ], 0.f);
                        oS[(c0+2*p+1)*128 + base] = fmaxf(hi + c2S[c0+2*p+1], 0.f);
                    }
                }
            }
        }
        __syncthreads();                     // (6) scatter done

        for(int i = tid; i < 4096; i += 256){
            int c = i >> 5, vq = i & 31;
            int s = (c >> 3) & 15;
            float4 v = *(const float4*)(oS + c*128 + ((vq ^ s) << 2));
            ((float4*)(ob + (size_t)c*G3))[vq] = v;
        }

        t = tn; p0 = q0; p1 = q1;
        __syncthreads();                     // (7) oS reads done, auxS rewrite safe
    }
}

// ---------------- launch ----------------
extern "C" void kernel_launch(void* const* d_in, const int* in_sizes, int n_in,
                              void* d_out, int out_size){
    const float* pc  = (const float*)d_in[0];
    const float* W1  = (const float*)d_in[1];
    const float* b1  = (const float*)d_in[2];
    const float* g1  = (const float*)d_in[3];
    const float* be1 = (const float*)d_in[4];
    const float* rm1 = (const float*)d_in[5];
    const float* rv1 = (const float*)d_in[6];
    const float* W2  = (const float*)d_in[7];
    const float* b2  = (const float*)d_in[8];
    const float* g2  = (const float*)d_in[9];
    const float* be2 = (const float*)d_in[10];
    const float* rm2 = (const float*)d_in[11];
    const float* rv2 = (const float*)d_in[12];

    cudaFuncSetAttribute(k_mlp, cudaFuncAttributeMaxDynamicSharedMemorySize, SM_FLOATS*4);

    k_prep<<<8192, 256>>>(W1,b1,g1,be1,rm1,rv1,W2,b2,g2,be2,rm2,rv2);
    k_minmax<<<dim3(64,4), 256>>>(pc);
    k_voxel<<<dim3(782,4), 256>>>(pc);
    k_mlp<<<304, 256, SM_FLOATS*4>>>((float*)d_out);
}

// round 7
// speedup vs baseline: 1.5254x; 1.1595x over previous
#include <cuda_runtime.h>
#include <cstdint>
#include <cstddef>

typedef unsigned long long ull;

#define GDIM 64
#define G3 (GDIM*GDIM*GDIM)
#define BATCH 4
#define NPTS 200000
#define MAXPV 35.0f
#define NTILES 8192

// ---------------- scratch ----------------
__device__ __align__(16) float g_accum[BATCH*G3*8];   // [b][voxel][8] = {sx,sy,sz,cnt, sr,sg,sb,pad}
__device__ unsigned g_minmax[BATCH*6];
__device__ float g_A1t[7*64];
__device__ float g_c1[64];
__device__ __align__(16) float g_A2[64*128];
__device__ float g_c2[128];
__device__ unsigned g_work;

// ---------------- helpers ----------------
__device__ __forceinline__ unsigned fenc(float f){
    unsigned u = __float_as_uint(f);
    return (u & 0x80000000u) ? ~u : (u | 0x80000000u);
}
__device__ __forceinline__ float fdec(unsigned u){
    return (u & 0x80000000u) ? __uint_as_float(u ^ 0x80000000u) : __uint_as_float(~u);
}
__device__ __forceinline__ void upk2(ull v, float& lo, float& hi){
    asm("mov.b64 {%0, %1}, %2;" : "=f"(lo), "=f"(hi) : "l"(v));
}
__device__ __forceinline__ void ffma2(ull& acc, ull x, ull y){
    asm("fma.rn.f32x2 %0, %1, %2, %0;" : "+l"(acc) : "l"(x), "l"(y));
}
__device__ __forceinline__ void lds2x64(ull& a, ull& b, unsigned addr){
    asm volatile("ld.shared.v2.b64 {%0, %1}, [%2];" : "=l"(a), "=l"(b) : "r"(addr));
}
__device__ __forceinline__ void red4(float* addr, float x, float y, float z, float w){
    asm volatile("red.global.add.v4.f32 [%0], {%1,%2,%3,%4};"
                 :: "l"(addr), "f"(x), "f"(y), "f"(z), "f"(w) : "memory");
}
__device__ __forceinline__ void cpasync16(unsigned saddr, const void* gaddr){
    asm volatile("cp.async.cg.shared.global [%0], [%1], 16;" :: "r"(saddr), "l"(gaddr));
}
__device__ __forceinline__ void cpasync_commit(){ asm volatile("cp.async.commit_group;"); }
__device__ __forceinline__ void cpasync_wait0(){ asm volatile("cp.async.wait_group 0;"); }

// ---------------- kernel 1: prep ----------------
__global__ void k_prep(const float* __restrict__ W1, const float* __restrict__ b1,
                       const float* __restrict__ g1, const float* __restrict__ be1,
                       const float* __restrict__ rm1, const float* __restrict__ rv1,
                       const float* __restrict__ W2, const float* __restrict__ b2,
                       const float* __restrict__ g2, const float* __restrict__ be2,
                       const float* __restrict__ rm2, const float* __restrict__ rv2){
    int i = blockIdx.x*blockDim.x + threadIdx.x;
    ((float4*)g_accum)[i] = make_float4(0.f,0.f,0.f,0.f);
    if(blockIdx.x == 0){
        int t = threadIdx.x;
        if(t < BATCH*6) g_minmax[t] = ((t % 6) < 3) ? 0xFFFFFFFFu : 0u;
        if(t == 0) g_work = 0u;
        if(t < 64){
            float s = g1[t] / sqrtf(rv1[t] + 1e-5f);
            g_c1[t] = (b1[t] - rm1[t]) * s + be1[t];
            #pragma unroll
            for(int k = 0; k < 7; k++) g_A1t[k*64 + t] = W1[t*7 + k] * s;
        }
        if(t < 128){
            float s = g2[t] / sqrtf(rv2[t] + 1e-5f);
            g_c2[t] = (b2[t] - rm2[t]) * s + be2[t];
            for(int k = 0; k < 64; k++) g_A2[k*128 + t] = W2[t*64 + k] * s;
        }
    }
}

// ---------------- kernel 2: min/max ----------------
__global__ void k_minmax(const float* __restrict__ pc){
    int b = blockIdx.y;
    const float* px = pc + b*6*NPTS;
    float mn0= 3.4e38f, mn1= 3.4e38f, mn2= 3.4e38f;
    float mx0=-3.4e38f, mx1=-3.4e38f, mx2=-3.4e38f;
    for(int n = blockIdx.x*blockDim.x + threadIdx.x; n < NPTS; n += gridDim.x*blockDim.x){
        float x = px[n], y = px[NPTS+n], z = px[2*NPTS+n];
        mn0 = fminf(mn0,x); mx0 = fmaxf(mx0,x);
        mn1 = fminf(mn1,y); mx1 = fmaxf(mx1,y);
        mn2 = fminf(mn2,z); mx2 = fmaxf(mx2,z);
    }
    #pragma unroll
    for(int s = 16; s; s >>= 1){
        mn0 = fminf(mn0, __shfl_xor_sync(~0u, mn0, s));
        mn1 = fminf(mn1, __shfl_xor_sync(~0u, mn1, s));
        mn2 = fminf(mn2, __shfl_xor_sync(~0u, mn2, s));
        mx0 = fmaxf(mx0, __shfl_xor_sync(~0u, mx0, s));
        mx1 = fmaxf(mx1, __shfl_xor_sync(~0u, mx1, s));
        mx2 = fmaxf(mx2, __shfl_xor_sync(~0u, mx2, s));
    }
    if((threadIdx.x & 31) == 0){
        atomicMin(&g_minmax[b*6+0], fenc(mn0));
        atomicMin(&g_minmax[b*6+1], fenc(mn1));
        atomicMin(&g_minmax[b*6+2], fenc(mn2));
        atomicMax(&g_minmax[b*6+3], fenc(mx0));
        atomicMax(&g_minmax[b*6+4], fenc(mx1));
        atomicMax(&g_minmax[b*6+5], fenc(mx2));
    }
}

// ---------------- kernel 3: voxel scatter ----------------
__global__ void k_voxel(const float* __restrict__ pc){
    int b = blockIdx.y;
    const float* p = pc + b*6*NPTS;
    float mn0 = fdec(g_minmax[b*6+0]);
    float mn1 = fdec(g_minmax[b*6+1]);
    float mn2 = fdec(g_minmax[b*6+2]);
    float d0 = fdec(g_minmax[b*6+3]) - mn0 + 1e-7f;
    float d1 = fdec(g_minmax[b*6+4]) - mn1 + 1e-7f;
    float d2 = fdec(g_minmax[b*6+5]) - mn2 + 1e-7f;
    float* acc = g_accum + (size_t)b*G3*8;
    for(int n = blockIdx.x*blockDim.x + threadIdx.x; n < NPTS; n += gridDim.x*blockDim.x){
        float x = p[n], y = p[NPTS+n], z = p[2*NPTS+n];
        float r = p[3*NPTS+n], g = p[4*NPTS+n], bl = p[5*NPTS+n];
        float tx = __fmul_rn(__fdiv_rn(x - mn0, d0), 63.0f);
        float ty = __fmul_rn(__fdiv_rn(y - mn1, d1), 63.0f);
        float tz = __fmul_rn(__fdiv_rn(z - mn2, d2), 63.0f);
        tx = fminf(fmaxf(tx, 0.0f), 62.9999f);
        ty = fminf(fmaxf(ty, 0.0f), 62.9999f);
        tz = fminf(fmaxf(tz, 0.0f), 62.9999f);
        int flat = (((int)tx)*GDIM + (int)ty)*GDIM + (int)tz;
        float* v = acc + (size_t)flat*8;
        red4(v,     x, y, z, 1.0f);
        red4(v + 4, r, g, bl, 0.0f);
    }
}

// ---------------- kernel 4: persistent fused MLP, paired tiles ----------------
#define SM_A2    0        // 8192 f  (32KB)
#define SM_H     8192     // 16384 f (64KB) : h-dup, later oS
#define SM_STAGE 24576    // 2048 f  (8KB)  : two tile stages (raw accum -> feats in-place)
#define SM_A1    26624    // 448 f
#define SM_C1    27072    // 64 f
#define SM_C2    27136    // 128 f
#define SM_PERM  27264    // 128 int
#define SM_AUX   27392    // 32 int
#define SM_OCCQ  27424    // 32 int
#define SM_FLOATS 27456   // 109824 bytes

template<int NC>
__device__ __forceinline__ void l2_body(unsigned aAddr, unsigned hAddr, ull (&a)[8][4]){
    #pragma unroll 4
    for(int k = 0; k < 64; k += 2){
        ull w00,w01,w02,w03, w10,w11,w12,w13;
        lds2x64(w00, w01, aAddr + (unsigned)k*512);
        lds2x64(w02, w03, aAddr + (unsigned)k*512 + 16);
        lds2x64(w10, w11, aAddr + (unsigned)k*512 + 512);
        lds2x64(w12, w13, aAddr + (unsigned)k*512 + 528);
        #pragma unroll
        for(int ch = 0; ch < NC; ch++){
            ull h0, h1;
            lds2x64(h0, h1, hAddr + (unsigned)ch*8192 + (unsigned)k*8);
            ffma2(a[ch][0], h0, w00);
            ffma2(a[ch][1], h0, w01);
            ffma2(a[ch][2], h0, w02);
            ffma2(a[ch][3], h0, w03);
            ffma2(a[ch][0], h1, w10);
            ffma2(a[ch][1], h1, w11);
            ffma2(a[ch][2], h1, w12);
            ffma2(a[ch][3], h1, w13);
        }
    }
}

// masked store of one tile from oS / direct zeros
__device__ __forceinline__ void store_tile(
    float* __restrict__ out, int id, int M, const int* balw,
    int slotBase, ull (&a)[8][4], float* sm, int* auxI, int* occQ,
    int tid, int cg, int vg, int c0)
{
    float* oS = sm + SM_H;
    float* c2S = sm + SM_C2;
    int* permS = (int*)(sm + SM_PERM);
    float* ob = out + (size_t)(id >> 11)*128*G3 + ((id & 2047) << 7);
    float4 z4 = make_float4(0.f,0.f,0.f,0.f);

    if(M == 0){
        for(int i = tid; i < 4096; i += 256){
            int c = i >> 5, q = i & 31;
            ((float4*)(ob + (size_t)c*G3))[q] = z4;
        }
        return;
    }

    // quad occupancy mask + list (warp 0)
    if(tid < 32){
        unsigned w = (unsigned)balw[tid >> 3];
        unsigned nib = (w >> ((tid & 7)*4)) & 0xFu;
        unsigned qb = __ballot_sync(0xFFFFFFFFu, nib != 0u);
        if(nib){
            int pos = __popc(qb & ((1u << tid) - 1u));
            occQ[pos] = tid;
        }
        if(tid == 0){ auxI[18] = (int)qb; auxI[19] = __popc(qb); }
    }
    __syncthreads();
    unsigned qmask = (unsigned)auxI[18];
    int nq = auxI[19];

    // zero only occupied quad columns
    for(int i = tid; i < nq*128; i += 256){
        int q = occQ[i >> 7], c = i & 127;
        *(float4*)(oS + c*128 + ((q ^ ((c >> 3) & 15)) << 2)) = z4;
    }
    __syncthreads();

    // scatter this tile's slots
    #pragma unroll
    for(int ch = 0; ch < 8; ch++){
        int slot = ch*16 + vg;
        if(slot >= slotBase && slot < slotBase + M){
            int v = permS[slot] & 127;
            int base = (((v >> 2) ^ cg) << 2) + (v & 3);
            #pragma unroll
            for(int p = 0; p < 4; p++){
                float lo, hi;
                upk2(a[ch][p], lo, hi);
                oS[(c0+2*p  )*128 + base] = fmaxf(lo + c2S[c0+2*p  ], 0.f);
                oS[(c0+2*p+1)*128 + base] = fmaxf(hi + c2S[c0+2*p+1], 0.f);
            }
        }
    }
    __syncthreads();

    // coalesced store: occupied quads from oS, rest zeros
    for(int i = tid; i < 4096; i += 256){
        int c = i >> 5, vq = i & 31;
        float4 v = ((qmask >> vq) & 1u)
            ? *(const float4*)(oS + c*128 + ((vq ^ ((c >> 3) & 15)) << 2)) : z4;
        ((float4*)(ob + (size_t)c*G3))[vq] = v;
    }
}

__global__ void __launch_bounds__(256, 2) k_mlp(float* __restrict__ out){
    extern __shared__ float sm[];
    float* A2S   = sm + SM_A2;
    float* stageF= sm + SM_STAGE;
    float* A1tS  = sm + SM_A1;
    float* c1S   = sm + SM_C1;
    float* c2S   = sm + SM_C2;
    int*   permS = (int*)(sm + SM_PERM);
    int*   auxI  = (int*)(sm + SM_AUX);
    int*   occQ  = (int*)(sm + SM_OCCQ);

    int tid = threadIdx.x;
    int cg = tid & 15, vg = tid >> 4;
    int c0 = cg*8;
    unsigned smemBase = (unsigned)__cvta_generic_to_shared(sm);
    unsigned hAddr = smemBase + SM_H*4 + (unsigned)vg*512;
    unsigned aAddr = smemBase + SM_A2*4 + (unsigned)c0*4;

    // prologue: weights once per block
    for(int i = tid; i < 448;  i += 256) A1tS[i] = g_A1t[i];
    if(tid < 64)  c1S[tid] = g_c1[tid];
    if(tid < 128) c2S[tid] = g_c2[tid];
    for(int i = tid; i < 2048; i += 256) ((float4*)A2S)[i] = ((const float4*)g_A2)[i];
    if(tid == 0){
        auxI[8] = (int)atomicAdd(&g_work, 1u);
        auxI[9] = (int)atomicAdd(&g_work, 1u);
    }
    __syncthreads();
    // initial prefetch of both sides
    #pragma unroll
    for(int s = 0; s < 2; s++){
        int id = auxI[8+s];
        if(tid < 128 && id < NTILES){
            const float* src = g_accum + (((size_t)(id >> 11))*G3 + ((id & 2047) << 7) + tid)*8;
            unsigned dst = smemBase + (SM_STAGE + s*1024 + tid*8)*4;
            cpasync16(dst, src); cpasync16(dst + 16, src + 4);
        }
    }
    cpasync_commit();
    int roleA = 0;

    while(true){
        cpasync_wait0();
        __syncthreads();                                   // S0

        int sA = roleA, sB = roleA ^ 1;
        int idA = auxI[8+sA], idB = auxI[8+sB];
        if(idA >= NTILES && idB >= NTILES) break;

        // ballots on raw counts
        float cntA = 0.f, cntB = 0.f;
        if(tid < 128){
            cntA = stageF[sA*1024 + tid*8 + 3];
            cntB = stageF[sB*1024 + tid*8 + 3];
        }
        int occA = (tid < 128) && (idA < NTILES) && (cntA > 0.f);
        int occB = (tid < 128) && (idB < NTILES) && (cntB > 0.f);
        unsigned balA = __ballot_sync(0xFFFFFFFFu, occA);
        unsigned balB = __ballot_sync(0xFFFFFFFFu, occB);
        if(tid < 128 && (tid & 31) == 0){
            int w = tid >> 5;
            auxI[w] = __popc(balA); auxI[4+w] = __popc(balB);
            auxI[10+w] = (int)balA; auxI[14+w] = (int)balB;
        }
        if(tid < 128) permS[tid] = -1;
        __syncthreads();                                   // S1

        int n0 = auxI[0], n1 = auxI[1], n2 = auxI[2], n3 = auxI[3];
        int m0 = auxI[4], m1 = auxI[5], m2 = auxI[6], m3 = auxI[7];
        int M1 = n0+n1+n2+n3, M2 = m0+m1+m2+m3;
        int c1n = (M1 + 15) >> 4, c2n = (M2 + 15) >> 4;
        bool consumeB = (idB < NTILES) && (c1n + c2n <= 8);
        int nch = c1n + (consumeB ? c2n : 0);

        // features in place (A always consumed; B only if consumed)
        if(occA){
            float* p = stageF + sA*1024 + tid*8;
            float4 r0 = *(float4*)p, r1 = *(float4*)(p+4);
            float cnt = r0.w, dn = fmaxf(cnt, 1.0f);
            r0.x = __fdiv_rn(r0.x, dn); r0.y = __fdiv_rn(r0.y, dn); r0.z = __fdiv_rn(r0.z, dn);
            r0.w = __fdiv_rn(fminf(cnt, MAXPV), MAXPV);
            r1.x = __fdiv_rn(r1.x, dn); r1.y = __fdiv_rn(r1.y, dn); r1.z = __fdiv_rn(r1.z, dn);
            r1.w = 0.f;
            *(float4*)p = r0; *(float4*)(p+4) = r1;
        }
        if(occB && consumeB){
            float* p = stageF + sB*1024 + tid*8;
            float4 r0 = *(float4*)p, r1 = *(float4*)(p+4);
            float cnt = r0.w, dn = fmaxf(cnt, 1.0f);
            r0.x = __fdiv_rn(r0.x, dn); r0.y = __fdiv_rn(r0.y, dn); r0.z = __fdiv_rn(r0.z, dn);
            r0.w = __fdiv_rn(fminf(cnt, MAXPV), MAXPV);
            r1.x = __fdiv_rn(r1.x, dn); r1.y = __fdiv_rn(r1.y, dn); r1.z = __fdiv_rn(r1.z, dn);
            r1.w = 0.f;
            *(float4*)p = r0; *(float4*)(p+4) = r1;
        }
        // perm writes
        if(occA){
            int w = tid >> 5;
            int off = (w > 0 ? n0 : 0) + (w > 1 ? n1 : 0) + (w > 2 ? n2 : 0);
            permS[off + __popc(balA & ((1u << (tid & 31)) - 1u))] = (sA << 7) | tid;
        }
        if(occB && consumeB){
            int w = tid >> 5;
            int off = (c1n << 4) + (w > 0 ? m0 : 0) + (w > 1 ? m1 : 0) + (w > 2 ? m2 : 0);
            permS[off + __popc(balB & ((1u << (tid & 31)) - 1u))] = (sB << 7) | tid;
        }
        // grab replacements
        if(tid == 0){
            auxI[8+sA] = (int)atomicAdd(&g_work, 1u);
            if(consumeB) auxI[8+sB] = (int)atomicAdd(&g_work, 1u);
        }
        __syncthreads();                                   // S2

        // layer 1 over group slots
        int Mp = nch << 4;
        float2* hS2 = (float2*)(sm + SM_H);
        for(int i = tid; i < Mp*64; i += 256){
            int slot = i >> 6, j = i & 63;
            int v = permS[slot];
            float h = 0.f;
            if(v >= 0){
                float s = c1S[j];
                const float* f = stageF + v*8;
                #pragma unroll
                for(int k = 0; k < 7; k++) s = fmaf(f[k], A1tS[k*64+j], s);
                h = fmaxf(s, 0.f);
            }
            hS2[slot*64 + j] = make_float2(h, h);
        }
        __syncthreads();                                   // S3 (stage reads done)

        // prefetch refilled sides (overlaps FMA + stores)
        {
            int nidA = auxI[8+sA];
            if(tid < 128 && nidA < NTILES){
                const float* src = g_accum + (((size_t)(nidA >> 11))*G3 + ((nidA & 2047) << 7) + tid)*8;
                unsigned dst = smemBase + (SM_STAGE + sA*1024 + tid*8)*4;
                cpasync16(dst, src); cpasync16(dst + 16, src + 4);
            }
            if(consumeB){
                int nidB = auxI[8+sB];
                if(tid < 128 && nidB < NTILES){
                    const float* src = g_accum + (((size_t)(nidB >> 11))*G3 + ((nidB & 2047) << 7) + tid)*8;
                    unsigned dst = smemBase + (SM_STAGE + sB*1024 + tid*8)*4;
                    cpasync16(dst, src); cpasync16(dst + 16, src + 4);
                }
            }
            cpasync_commit();
        }

        // layer 2
        ull a[8][4];
        #pragma unroll
        for(int ch = 0; ch < 8; ch++)
            #pragma unroll
            for(int p = 0; p < 4; p++) a[ch][p] = 0ull;
        switch(nch){
            case 0: break;
            case 1: l2_body<1>(aAddr, hAddr, a); break;
            case 2: l2_body<2>(aAddr, hAddr, a); break;
            case 3: l2_body<3>(aAddr, hAddr, a); break;
            case 4: l2_body<4>(aAddr, hAddr, a); break;
            case 5: l2_body<5>(aAddr, hAddr, a); break;
            case 6: l2_body<6>(aAddr, hAddr, a); break;
            case 7: l2_body<7>(aAddr, hAddr, a); break;
            default: l2_body<8>(aAddr, hAddr, a); break;
        }
        __syncthreads();                                   // S4 (h reads done -> oS free)

        // stores
        if(idA < NTILES)
            store_tile(out, idA, M1, auxI+10, 0, a, sm, auxI, occQ, tid, cg, vg, c0);
        if(consumeB && idB < NTILES){
            __syncthreads();
            store_tile(out, idB, M2, auxI+14, c1n << 4, a, sm, auxI, occQ, tid, cg, vg, c0);
        }

        if(!consumeB) roleA ^= 1;
        __syncthreads();                                   // protect aux/perm/oS for next iter
    }
}

// ---------------- launch ----------------
extern "C" void kernel_launch(void* const* d_in, const int* in_sizes, int n_in,
                              void* d_out, int out_size){
    const float* pc  = (const float*)d_in[0];
    const float* W1  = (const float*)d_in[1];
    const float* b1  = (const float*)d_in[2];
    const float* g1  = (const float*)d_in[3];
    const float* be1 = (const float*)d_in[4];
    const float* rm1 = (const float*)d_in[5];
    const float* rv1 = (const float*)d_in[6];
    const float* W2  = (const float*)d_in[7];
    const float* b2  = (const float*)d_in[8];
    const float* g2  = (const float*)d_in[9];
    const float* be2 = (const float*)d_in[10];
    const float* rm2 = (const float*)d_in[11];
    const float* rv2 = (const float*)d_in[12];

    cudaFuncSetAttribute(k_mlp, cudaFuncAttributeMaxDynamicSharedMemorySize, SM_FLOATS*4);

    k_prep<<<8192, 256>>>(W1,b1,g1,be1,rm1,rv1,W2,b2,g2,be2,rm2,rv2);
    k_minmax<<<dim3(64,4), 256>>>(pc);
    k_voxel<<<dim3(782,4), 256>>>(pc);
    k_mlp<<<304, 256, SM_FLOATS*4>>>((float*)d_out);
}

// round 8
// speedup vs baseline: 1.6093x; 1.0550x over previous
#include <cuda_runtime.h>
#include <cstdint>
#include <cstddef>

typedef unsigned long long ull;

#define GDIM 64
#define G3 (GDIM*GDIM*GDIM)
#define BATCH 4
#define NPTS 200000
#define MAXPV 35.0f
#define MAXOCC 800000          // hard bound: <= NPTS occupied voxels per batch

// ---------------- scratch ----------------
__device__ __align__(16) float g_accum[BATCH*G3*8];   // [b][voxel][8] = {sx,sy,sz,cnt, sr,sg,sb,pad}
__device__ unsigned g_minmax[BATCH*6];
__device__ float g_A1t[7*64];
__device__ float g_c1[64];
__device__ __align__(16) float g_A2[64*128];
__device__ float g_c2[128];
__device__ unsigned g_nocc;
__device__ __align__(16) int   g_index[BATCH*G3];     // voxel -> compact pos or -1
__device__ __align__(16) float g_feat[MAXOCC*8];      // compact features
__device__ __align__(16) float g_comp[(size_t)MAXOCC*128]; // compact outputs

// ---------------- helpers ----------------
__device__ __forceinline__ unsigned fenc(float f){
    unsigned u = __float_as_uint(f);
    return (u & 0x80000000u) ? ~u : (u | 0x80000000u);
}
__device__ __forceinline__ float fdec(unsigned u){
    return (u & 0x80000000u) ? __uint_as_float(u ^ 0x80000000u) : __uint_as_float(~u);
}
__device__ __forceinline__ void upk2(ull v, float& lo, float& hi){
    asm("mov.b64 {%0, %1}, %2;" : "=f"(lo), "=f"(hi) : "l"(v));
}
__device__ __forceinline__ void ffma2(ull& acc, ull x, ull y){
    asm("fma.rn.f32x2 %0, %1, %2, %0;" : "+l"(acc) : "l"(x), "l"(y));
}
__device__ __forceinline__ void lds2x64(ull& a, ull& b, unsigned addr){
    asm volatile("ld.shared.v2.b64 {%0, %1}, [%2];" : "=l"(a), "=l"(b) : "r"(addr));
}
__device__ __forceinline__ void red4(float* addr, float x, float y, float z, float w){
    asm volatile("red.global.add.v4.f32 [%0], {%1,%2,%3,%4};"
                 :: "l"(addr), "f"(x), "f"(y), "f"(z), "f"(w) : "memory");
}

// ---------------- kernel 1: prep ----------------
__global__ void k_prep(const float* __restrict__ W1, const float* __restrict__ b1,
                       const float* __restrict__ g1, const float* __restrict__ be1,
                       const float* __restrict__ rm1, const float* __restrict__ rv1,
                       const float* __restrict__ W2, const float* __restrict__ b2,
                       const float* __restrict__ g2, const float* __restrict__ be2,
                       const float* __restrict__ rm2, const float* __restrict__ rv2){
    int i = blockIdx.x*blockDim.x + threadIdx.x;
    ((float4*)g_accum)[i] = make_float4(0.f,0.f,0.f,0.f);
    if(blockIdx.x == 0){
        int t = threadIdx.x;
        if(t < BATCH*6) g_minmax[t] = ((t % 6) < 3) ? 0xFFFFFFFFu : 0u;
        if(t == 0) g_nocc = 0u;
        if(t < 64){
            float s = g1[t] / sqrtf(rv1[t] + 1e-5f);
            g_c1[t] = (b1[t] - rm1[t]) * s + be1[t];
            #pragma unroll
            for(int k = 0; k < 7; k++) g_A1t[k*64 + t] = W1[t*7 + k] * s;
        }
        if(t < 128){
            float s = g2[t] / sqrtf(rv2[t] + 1e-5f);
            g_c2[t] = (b2[t] - rm2[t]) * s + be2[t];
            for(int k = 0; k < 64; k++) g_A2[k*128 + t] = W2[t*64 + k] * s;
        }
    }
}

// ---------------- kernel 2: min/max ----------------
__global__ void k_minmax(const float* __restrict__ pc){
    int b = blockIdx.y;
    const float* px = pc + b*6*NPTS;
    float mn0= 3.4e38f, mn1= 3.4e38f, mn2= 3.4e38f;
    float mx0=-3.4e38f, mx1=-3.4e38f, mx2=-3.4e38f;
    for(int n = blockIdx.x*blockDim.x + threadIdx.x; n < NPTS; n += gridDim.x*blockDim.x){
        float x = px[n], y = px[NPTS+n], z = px[2*NPTS+n];
        mn0 = fminf(mn0,x); mx0 = fmaxf(mx0,x);
        mn1 = fminf(mn1,y); mx1 = fmaxf(mx1,y);
        mn2 = fminf(mn2,z); mx2 = fmaxf(mx2,z);
    }
    #pragma unroll
    for(int s = 16; s; s >>= 1){
        mn0 = fminf(mn0, __shfl_xor_sync(~0u, mn0, s));
        mn1 = fminf(mn1, __shfl_xor_sync(~0u, mn1, s));
        mn2 = fminf(mn2, __shfl_xor_sync(~0u, mn2, s));
        mx0 = fmaxf(mx0, __shfl_xor_sync(~0u, mx0, s));
        mx1 = fmaxf(mx1, __shfl_xor_sync(~0u, mx1, s));
        mx2 = fmaxf(mx2, __shfl_xor_sync(~0u, mx2, s));
    }
    if((threadIdx.x & 31) == 0){
        atomicMin(&g_minmax[b*6+0], fenc(mn0));
        atomicMin(&g_minmax[b*6+1], fenc(mn1));
        atomicMin(&g_minmax[b*6+2], fenc(mn2));
        atomicMax(&g_minmax[b*6+3], fenc(mx0));
        atomicMax(&g_minmax[b*6+4], fenc(mx1));
        atomicMax(&g_minmax[b*6+5], fenc(mx2));
    }
}

// ---------------- kernel 3: voxel scatter ----------------
__global__ void k_voxel(const float* __restrict__ pc){
    int b = blockIdx.y;
    const float* p = pc + b*6*NPTS;
    float mn0 = fdec(g_minmax[b*6+0]);
    float mn1 = fdec(g_minmax[b*6+1]);
    float mn2 = fdec(g_minmax[b*6+2]);
    float d0 = fdec(g_minmax[b*6+3]) - mn0 + 1e-7f;
    float d1 = fdec(g_minmax[b*6+4]) - mn1 + 1e-7f;
    float d2 = fdec(g_minmax[b*6+5]) - mn2 + 1e-7f;
    float* acc = g_accum + (size_t)b*G3*8;
    for(int n = blockIdx.x*blockDim.x + threadIdx.x; n < NPTS; n += gridDim.x*blockDim.x){
        float x = p[n], y = p[NPTS+n], z = p[2*NPTS+n];
        float r = p[3*NPTS+n], g = p[4*NPTS+n], bl = p[5*NPTS+n];
        float tx = __fmul_rn(__fdiv_rn(x - mn0, d0), 63.0f);
        float ty = __fmul_rn(__fdiv_rn(y - mn1, d1), 63.0f);
        float tz = __fmul_rn(__fdiv_rn(z - mn2, d2), 63.0f);
        tx = fminf(fmaxf(tx, 0.0f), 62.9999f);
        ty = fminf(fmaxf(ty, 0.0f), 62.9999f);
        tz = fminf(fmaxf(tz, 0.0f), 62.9999f);
        int flat = (((int)tx)*GDIM + (int)ty)*GDIM + (int)tz;
        float* v = acc + (size_t)flat*8;
        red4(v,     x, y, z, 1.0f);
        red4(v + 4, r, g, bl, 0.0f);
    }
}

// ---------------- kernel 4: global compaction + feature computation ----------------
__global__ void k_compact(){
    int gv = blockIdx.x*256 + threadIdx.x;     // grid 4096 covers BATCH*G3
    float4 p0 = *(const float4*)(g_accum + (size_t)gv*8);
    int occ = p0.w > 0.f;
    unsigned bal = __ballot_sync(0xFFFFFFFFu, occ);
    int nw = __popc(bal);
    unsigned base = 0;
    if((threadIdx.x & 31) == 0 && nw) base = atomicAdd(&g_nocc, (unsigned)nw);
    base = __shfl_sync(0xFFFFFFFFu, base, 0);
    if(occ){
        int pos = (int)base + __popc(bal & ((1u << (threadIdx.x & 31)) - 1u));
        g_index[gv] = pos;
        float4 p1 = *(const float4*)(g_accum + (size_t)gv*8 + 4);
        float cnt = p0.w, dn = fmaxf(cnt, 1.0f);
        float* f = g_feat + (size_t)pos*8;
        f[0] = __fdiv_rn(p0.x, dn);
        f[1] = __fdiv_rn(p0.y, dn);
        f[2] = __fdiv_rn(p0.z, dn);
        f[3] = __fdiv_rn(fminf(cnt, MAXPV), MAXPV);
        f[4] = __fdiv_rn(p1.x, dn);
        f[5] = __fdiv_rn(p1.y, dn);
        f[6] = __fdiv_rn(p1.z, dn);
        f[7] = 0.f;
    } else {
        g_index[gv] = -1;
    }
}

// ---------------- kernel 5: dense MLP over compacted voxels ----------------
#define SG_A2    0        // 8192 f
#define SG_H     8192     // 16384 f
#define SG_FEAT  24576    // 1024 f
#define SG_A1    25600    // 448 f
#define SG_C1    26112    // 64 f
#define SG_C2    26176    // 128 f
#define SG_FLOATS 26304   // 105216 bytes

__device__ __forceinline__ void l2_full(unsigned aAddr, unsigned hAddr, ull (&a)[8][4]){
    #pragma unroll 4
    for(int k = 0; k < 64; k += 2){
        ull w00,w01,w02,w03, w10,w11,w12,w13;
        lds2x64(w00, w01, aAddr + (unsigned)k*512);
        lds2x64(w02, w03, aAddr + (unsigned)k*512 + 16);
        lds2x64(w10, w11, aAddr + (unsigned)k*512 + 512);
        lds2x64(w12, w13, aAddr + (unsigned)k*512 + 528);
        #pragma unroll
        for(int ch = 0; ch < 8; ch++){
            ull h0, h1;
            lds2x64(h0, h1, hAddr + (unsigned)ch*8192 + (unsigned)k*8);
            ffma2(a[ch][0], h0, w00);
            ffma2(a[ch][1], h0, w01);
            ffma2(a[ch][2], h0, w02);
            ffma2(a[ch][3], h0, w03);
            ffma2(a[ch][0], h1, w10);
            ffma2(a[ch][1], h1, w11);
            ffma2(a[ch][2], h1, w12);
            ffma2(a[ch][3], h1, w13);
        }
    }
}

__global__ void __launch_bounds__(256, 2) k_gemm(){
    extern __shared__ float sm[];
    int N = (int)g_nocc;
    int base = blockIdx.x << 7;
    if(base >= N) return;

    float* A2S   = sm + SG_A2;
    float* featS = sm + SG_FEAT;
    float* A1tS  = sm + SG_A1;
    float* c1S   = sm + SG_C1;
    float* c2S   = sm + SG_C2;
    int tid = threadIdx.x;
    int cg = tid & 15, vg = tid >> 4;
    int c0 = cg*8;
    unsigned smemBase = (unsigned)__cvta_generic_to_shared(sm);
    unsigned hAddr = smemBase + SG_H*4 + (unsigned)vg*512;
    unsigned aAddr = smemBase + SG_A2*4 + (unsigned)c0*4;

    // weights + feats
    for(int i = tid; i < 448;  i += 256) A1tS[i] = g_A1t[i];
    if(tid < 64)  c1S[tid] = g_c1[tid];
    if(tid < 128) c2S[tid] = g_c2[tid];
    for(int i = tid; i < 2048; i += 256) ((float4*)A2S)[i] = ((const float4*)g_A2)[i];
    for(int i = tid; i < 512; i += 256){
        float2 v = make_float2(0.f, 0.f);
        if(base*8 + i*2 < N*8) v = ((const float2*)(g_feat + (size_t)base*8))[i];
        ((float2*)featS)[i] = v;
    }
    __syncthreads();

    // layer 1 (h pre-duplicated)
    float2* hS2 = (float2*)(sm + SG_H);
    for(int i = tid; i < 8192; i += 256){
        int slot = i >> 6, j = i & 63;
        float h = 0.f;
        if(base + slot < N){
            float s = c1S[j];
            const float* f = featS + slot*8;
            #pragma unroll
            for(int k = 0; k < 7; k++) s = fmaf(f[k], A1tS[k*64+j], s);
            h = fmaxf(s, 0.f);
        }
        hS2[slot*64 + j] = make_float2(h, h);
    }
    __syncthreads();

    // layer 2, always full 8 chunks
    ull a[8][4];
    #pragma unroll
    for(int ch = 0; ch < 8; ch++)
        #pragma unroll
        for(int p = 0; p < 4; p++) a[ch][p] = 0ull;
    l2_full(aAddr, hAddr, a);

    // epilogue: bias + relu, coalesced compact stores
    #pragma unroll
    for(int ch = 0; ch < 8; ch++){
        int slot = ch*16 + vg;
        if(base + slot < N){
            float o[8];
            #pragma unroll
            for(int p = 0; p < 4; p++){
                float lo, hi;
                upk2(a[ch][p], lo, hi);
                o[2*p  ] = fmaxf(lo + c2S[c0+2*p  ], 0.f);
                o[2*p+1] = fmaxf(hi + c2S[c0+2*p+1], 0.f);
            }
            float* dst = g_comp + (size_t)(base + slot)*128 + c0;
            *(float4*)(dst)     = make_float4(o[0], o[1], o[2], o[3]);
            *(float4*)(dst + 4) = make_float4(o[4], o[5], o[6], o[7]);
        }
    }
}

// ---------------- kernel 6: bandwidth fill (gather + transpose + stream) ----------------
#define SF_O     0        // 16384 f
#define SF_IDX   16384    // 128 ints
#define SF_FLOATS 16512   // 66048 bytes

__global__ void __launch_bounds__(256, 3) k_fill(float* __restrict__ out){
    extern __shared__ float sm[];
    float* oS = sm + SF_O;
    int* idxS = (int*)(sm + SF_IDX);

    int tid = threadIdx.x;
    int t = blockIdx.x;
    int b = t >> 11;
    int vbase = (t & 2047) << 7;
    if(tid < 128) idxS[tid] = g_index[b*G3 + vbase + tid];
    int any = __syncthreads_or(tid < 128 && idxS[tid] >= 0);

    float* ob = out + (size_t)b*128*G3 + vbase;
    float4 z4 = make_float4(0.f,0.f,0.f,0.f);
    if(!any){
        for(int i = tid; i < 4096; i += 256){
            int c = i >> 5, q = i & 31;
            ((float4*)(ob + (size_t)c*G3))[q] = z4;
        }
        return;
    }

    for(int i = tid; i < 4096; i += 256) ((float4*)oS)[i] = z4;
    __syncthreads();

    int cg = tid & 15, vg = tid >> 4;
    int c0 = cg*8;
    #pragma unroll
    for(int vi = 0; vi < 8; vi++){
        int v = vg*8 + vi;
        int ix = idxS[v];
        if(ix >= 0){
            const float* src = g_comp + (size_t)ix*128 + c0;
            float4 r0 = *(const float4*)(src);
            float4 r1 = *(const float4*)(src + 4);
            int basei = (((v >> 2) ^ cg) << 2) + (v & 3);
            oS[(c0+0)*128 + basei] = r0.x;
            oS[(c0+1)*128 + basei] = r0.y;
            oS[(c0+2)*128 + basei] = r0.z;
            oS[(c0+3)*128 + basei] = r0.w;
            oS[(c0+4)*128 + basei] = r1.x;
            oS[(c0+5)*128 + basei] = r1.y;
            oS[(c0+6)*128 + basei] = r1.z;
            oS[(c0+7)*128 + basei] = r1.w;
        }
    }
    __syncthreads();

    for(int i = tid; i < 4096; i += 256){
        int c = i >> 5, vq = i & 31;
        int s = (c >> 3) & 15;
        float4 v = *(const float4*)(oS + c*128 + ((vq ^ s) << 2));
        ((float4*)(ob + (size_t)c*G3))[vq] = v;
    }
}

// ---------------- launch ----------------
extern "C" void kernel_launch(void* const* d_in, const int* in_sizes, int n_in,
                              void* d_out, int out_size){
    const float* pc  = (const float*)d_in[0];
    const float* W1  = (const float*)d_in[1];
    const float* b1  = (const float*)d_in[2];
    const float* g1  = (const float*)d_in[3];
    const float* be1 = (const float*)d_in[4];
    const float* rm1 = (const float*)d_in[5];
    const float* rv1 = (const float*)d_in[6];
    const float* W2  = (const float*)d_in[7];
    const float* b2  = (const float*)d_in[8];
    const float* g2  = (const float*)d_in[9];
    const float* be2 = (const float*)d_in[10];
    const float* rm2 = (const float*)d_in[11];
    const float* rv2 = (const float*)d_in[12];

    cudaFuncSetAttribute(k_gemm, cudaFuncAttributeMaxDynamicSharedMemorySize, SG_FLOATS*4);
    cudaFuncSetAttribute(k_fill, cudaFuncAttributeMaxDynamicSharedMemorySize, SF_FLOATS*4);

    k_prep<<<8192, 256>>>(W1,b1,g1,be1,rm1,rv1,W2,b2,g2,be2,rm2,rv2);
    k_minmax<<<dim3(64,4), 256>>>(pc);
    k_voxel<<<dim3(782,4), 256>>>(pc);
    k_compact<<<4096, 256>>>();
    k_gemm<<<MAXOCC/128, 256, SG_FLOATS*4>>>();
    k_fill<<<BATCH*2048, 256, SF_FLOATS*4>>>((float*)d_out);
}

// round 9
// speedup vs baseline: 1.8143x; 1.1273x over previous
#include <cuda_runtime.h>
#include <cstdint>
#include <cstddef>

typedef unsigned long long ull;

#define GDIM 64
#define G3 (GDIM*GDIM*GDIM)
#define BATCH 4
#define NPTS 200000
#define MAXPV 35.0f
#define MAXOCC 800000

// ---------------- scratch ----------------
__device__ __align__(16) float g_accum[BATCH*G3*8];
__device__ float g_mm2[BATCH*64*6];                   // per-block minmax partials: [b][blk][{mn0,mn1,mn2,mx0,mx1,mx2}]
__device__ float g_A1t[7*64];
__device__ float g_c1[64];
__device__ __align__(16) float g_A2[64*128];
__device__ float g_c2[128];
__device__ unsigned g_nocc;
__device__ __align__(16) int   g_index[BATCH*G3];
__device__ __align__(16) float g_feat[(size_t)MAXOCC*8 + 1024];
__device__ __align__(16) float g_comp[(size_t)MAXOCC*128 + 1024];

// ---------------- helpers ----------------
__device__ __forceinline__ void upk2(ull v, float& lo, float& hi){
    asm("mov.b64 {%0, %1}, %2;" : "=f"(lo), "=f"(hi) : "l"(v));
}
__device__ __forceinline__ void ffma2(ull& acc, ull x, ull y){
    asm("fma.rn.f32x2 %0, %1, %2, %0;" : "+l"(acc) : "l"(x), "l"(y));
}
__device__ __forceinline__ void lds2x64(ull& a, ull& b, unsigned addr){
    asm volatile("ld.shared.v2.b64 {%0, %1}, [%2];" : "=l"(a), "=l"(b) : "r"(addr));
}
__device__ __forceinline__ void red4(float* addr, float x, float y, float z, float w){
    asm volatile("red.global.add.v4.f32 [%0], {%1,%2,%3,%4};"
                 :: "l"(addr), "f"(x), "f"(y), "f"(z), "f"(w) : "memory");
}

// ---------------- kernel 1: prep (zero accum + fuse weights + minmax partials) ----------------
__global__ void k_prep(const float* __restrict__ W1, const float* __restrict__ b1,
                       const float* __restrict__ g1, const float* __restrict__ be1,
                       const float* __restrict__ rm1, const float* __restrict__ rv1,
                       const float* __restrict__ W2, const float* __restrict__ b2,
                       const float* __restrict__ g2, const float* __restrict__ be2,
                       const float* __restrict__ rm2, const float* __restrict__ rv2,
                       const float* __restrict__ pc){
    if(blockIdx.x < 8192){
        int i = blockIdx.x*256 + threadIdx.x;
        ((float4*)g_accum)[i] = make_float4(0.f,0.f,0.f,0.f);
        if(blockIdx.x == 0){
            int t = threadIdx.x;
            if(t == 0) g_nocc = 0u;
            if(t < 64){
                float s = g1[t] / sqrtf(rv1[t] + 1e-5f);
                g_c1[t] = (b1[t] - rm1[t]) * s + be1[t];
                #pragma unroll
                for(int k = 0; k < 7; k++) g_A1t[k*64 + t] = W1[t*7 + k] * s;
            }
            if(t < 128){
                float s = g2[t] / sqrtf(rv2[t] + 1e-5f);
                g_c2[t] = (b2[t] - rm2[t]) * s + be2[t];
                for(int k = 0; k < 64; k++) g_A2[k*128 + t] = W2[t*64 + k] * s;
            }
        }
        return;
    }
    // minmax partial blocks
    int m = blockIdx.x - 8192;          // 0..255
    int b = m >> 6, mloc = m & 63;
    const float* px = pc + b*6*NPTS;
    float mn0= 3.4e38f, mn1= 3.4e38f, mn2= 3.4e38f;
    float mx0=-3.4e38f, mx1=-3.4e38f, mx2=-3.4e38f;
    for(int n = mloc*256 + threadIdx.x; n < NPTS; n += 64*256){
        float x = px[n], y = px[NPTS+n], z = px[2*NPTS+n];
        mn0 = fminf(mn0,x); mx0 = fmaxf(mx0,x);
        mn1 = fminf(mn1,y); mx1 = fmaxf(mx1,y);
        mn2 = fminf(mn2,z); mx2 = fmaxf(mx2,z);
    }
    #pragma unroll
    for(int s = 16; s; s >>= 1){
        mn0 = fminf(mn0, __shfl_xor_sync(~0u, mn0, s));
        mn1 = fminf(mn1, __shfl_xor_sync(~0u, mn1, s));
        mn2 = fminf(mn2, __shfl_xor_sync(~0u, mn2, s));
        mx0 = fmaxf(mx0, __shfl_xor_sync(~0u, mx0, s));
        mx1 = fmaxf(mx1, __shfl_xor_sync(~0u, mx1, s));
        mx2 = fmaxf(mx2, __shfl_xor_sync(~0u, mx2, s));
    }
    __shared__ float wred[8][6];
    int wid = threadIdx.x >> 5;
    if((threadIdx.x & 31) == 0){
        wred[wid][0]=mn0; wred[wid][1]=mn1; wred[wid][2]=mn2;
        wred[wid][3]=mx0; wred[wid][4]=mx1; wred[wid][5]=mx2;
    }
    __syncthreads();
    if(threadIdx.x < 6){
        int c = threadIdx.x;
        bool isMin = c < 3;
        float acc = wred[0][c];
        #pragma unroll
        for(int w = 1; w < 8; w++) acc = isMin ? fminf(acc, wred[w][c]) : fmaxf(acc, wred[w][c]);
        g_mm2[m*6 + c] = acc;
    }
}

// ---------------- kernel 2: voxel scatter (reduces partials per block) ----------------
__global__ void k_voxel(const float* __restrict__ pc){
    int b = blockIdx.y;
    __shared__ float red[6];
    {
        int wid = threadIdx.x >> 5, lid = threadIdx.x & 31;
        if(wid < 6){
            bool isMin = wid < 3;
            float acc = isMin ? 3.4e38f : -3.4e38f;
            for(int m = lid; m < 64; m += 32){
                float v = g_mm2[(b*64 + m)*6 + wid];
                acc = isMin ? fminf(acc, v) : fmaxf(acc, v);
            }
            #pragma unroll
            for(int s = 16; s; s >>= 1){
                float o = __shfl_xor_sync(~0u, acc, s);
                acc = isMin ? fminf(acc, o) : fmaxf(acc, o);
            }
            if(lid == 0) red[wid] = acc;
        }
        __syncthreads();
    }
    float mn0 = red[0], mn1 = red[1], mn2 = red[2];
    float d0 = red[3] - mn0 + 1e-7f;
    float d1 = red[4] - mn1 + 1e-7f;
    float d2 = red[5] - mn2 + 1e-7f;

    const float* p = pc + b*6*NPTS;
    float* acc = g_accum + (size_t)b*G3*8;
    for(int n = blockIdx.x*blockDim.x + threadIdx.x; n < NPTS; n += gridDim.x*blockDim.x){
        float x = p[n], y = p[NPTS+n], z = p[2*NPTS+n];
        float r = p[3*NPTS+n], g = p[4*NPTS+n], bl = p[5*NPTS+n];
        float tx = __fmul_rn(__fdiv_rn(x - mn0, d0), 63.0f);
        float ty = __fmul_rn(__fdiv_rn(y - mn1, d1), 63.0f);
        float tz = __fmul_rn(__fdiv_rn(z - mn2, d2), 63.0f);
        tx = fminf(fmaxf(tx, 0.0f), 62.9999f);
        ty = fminf(fmaxf(ty, 0.0f), 62.9999f);
        tz = fminf(fmaxf(tz, 0.0f), 62.9999f);
        int flat = (((int)tx)*GDIM + (int)ty)*GDIM + (int)tz;
        float* v = acc + (size_t)flat*8;
        red4(v,     x, y, z, 1.0f);
        red4(v + 4, r, g, bl, 0.0f);
    }
}

// ---------------- kernel 3: compaction, 4 voxels/thread ----------------
__global__ void k_compact(){
    int t = blockIdx.x*256 + threadIdx.x;
    int gv0 = t*4;
    unsigned lane = threadIdx.x & 31;

    float4 p0[4];
    #pragma unroll
    for(int v = 0; v < 4; v++) p0[v] = *(const float4*)(g_accum + (size_t)(gv0+v)*8);

    int cnt = 0;
    #pragma unroll
    for(int v = 0; v < 4; v++) cnt += (p0[v].w > 0.f);

    // warp inclusive scan of cnt
    int x = cnt;
    #pragma unroll
    for(int d = 1; d < 32; d <<= 1){
        int y = __shfl_up_sync(0xFFFFFFFFu, x, d);
        if(lane >= d) x += y;
    }
    int excl = x - cnt;
    int total = __shfl_sync(0xFFFFFFFFu, x, 31);
    unsigned base = 0;
    if(lane == 31 && total) base = atomicAdd(&g_nocc, (unsigned)total);
    base = __shfl_sync(0xFFFFFFFFu, base, 31);

    int pos = (int)base + excl;
    int4 idx;
    int* ip = (int*)&idx;
    #pragma unroll
    for(int v = 0; v < 4; v++){
        if(p0[v].w > 0.f){
            ip[v] = pos;
            float4 p1 = *(const float4*)(g_accum + (size_t)(gv0+v)*8 + 4);
            float cntv = p0[v].w, dn = fmaxf(cntv, 1.0f);
            float* f = g_feat + (size_t)pos*8;
            f[0] = __fdiv_rn(p0[v].x, dn);
            f[1] = __fdiv_rn(p0[v].y, dn);
            f[2] = __fdiv_rn(p0[v].z, dn);
            f[3] = __fdiv_rn(fminf(cntv, MAXPV), MAXPV);
            f[4] = __fdiv_rn(p1.x, dn);
            f[5] = __fdiv_rn(p1.y, dn);
            f[6] = __fdiv_rn(p1.z, dn);
            f[7] = 0.f;
            pos++;
        } else {
            ip[v] = -1;
        }
    }
    *(int4*)(g_index + gv0) = idx;
}

// ---------------- kernel 4: dense MLP over compacted voxels ----------------
#define SG_A2    0
#define SG_H     8192
#define SG_FEAT  24576
#define SG_A1    25600
#define SG_C1    26112
#define SG_C2    26176
#define SG_FLOATS 26304   // 105216 bytes

__device__ __forceinline__ void l2_full(unsigned aAddr, unsigned hAddr, ull (&a)[8][4]){
    #pragma unroll 4
    for(int k = 0; k < 64; k += 2){
        ull w00,w01,w02,w03, w10,w11,w12,w13;
        lds2x64(w00, w01, aAddr + (unsigned)k*512);
        lds2x64(w02, w03, aAddr + (unsigned)k*512 + 16);
        lds2x64(w10, w11, aAddr + (unsigned)k*512 + 512);
        lds2x64(w12, w13, aAddr + (unsigned)k*512 + 528);
        #pragma unroll
        for(int ch = 0; ch < 8; ch++){
            ull h0, h1;
            lds2x64(h0, h1, hAddr + (unsigned)ch*8192 + (unsigned)k*8);
            ffma2(a[ch][0], h0, w00);
            ffma2(a[ch][1], h0, w01);
            ffma2(a[ch][2], h0, w02);
            ffma2(a[ch][3], h0, w03);
            ffma2(a[ch][0], h1, w10);
            ffma2(a[ch][1], h1, w11);
            ffma2(a[ch][2], h1, w12);
            ffma2(a[ch][3], h1, w13);
        }
    }
}

__global__ void __launch_bounds__(256, 2) k_gemm(){
    extern __shared__ float sm[];
    int N = (int)g_nocc;
    int base = blockIdx.x << 7;
    if(base >= N) return;

    float* A2S   = sm + SG_A2;
    float* featS = sm + SG_FEAT;
    float* A1tS  = sm + SG_A1;
    float* c1S   = sm + SG_C1;
    float* c2S   = sm + SG_C2;
    int tid = threadIdx.x;
    int cg = tid & 15, vg = tid >> 4;
    int c0 = cg*8;
    unsigned smemBase = (unsigned)__cvta_generic_to_shared(sm);
    unsigned hAddr = smemBase + SG_H*4 + (unsigned)vg*512;
    unsigned aAddr = smemBase + SG_A2*4 + (unsigned)c0*4;

    // weights + feats (unconditional; padded region of g_feat is benign)
    for(int i = tid; i < 512; i += 256)
        ((float2*)featS)[i] = ((const float2*)(g_feat + (size_t)base*8))[i];
    for(int i = tid; i < 448;  i += 256) A1tS[i] = g_A1t[i];
    if(tid < 64)  c1S[tid] = g_c1[tid];
    if(tid < 128) c2S[tid] = g_c2[tid];
    for(int i = tid; i < 2048; i += 256) ((float4*)A2S)[i] = ((const float4*)g_A2)[i];
    __syncthreads();

    // layer 1 (h pre-duplicated), no boundary guards
    float2* hS2 = (float2*)(sm + SG_H);
    for(int i = tid; i < 8192; i += 256){
        int slot = i >> 6, j = i & 63;
        float s = c1S[j];
        const float* f = featS + slot*8;
        #pragma unroll
        for(int k = 0; k < 7; k++) s = fmaf(f[k], A1tS[k*64+j], s);
        float h = fmaxf(s, 0.f);
        hS2[slot*64 + j] = make_float2(h, h);
    }
    __syncthreads();

    // layer 2
    ull a[8][4];
    #pragma unroll
    for(int ch = 0; ch < 8; ch++)
        #pragma unroll
        for(int p = 0; p < 4; p++) a[ch][p] = 0ull;
    l2_full(aAddr, hAddr, a);

    // epilogue: bias + relu, coalesced compact stores (padded rows never read)
    #pragma unroll
    for(int ch = 0; ch < 8; ch++){
        int slot = ch*16 + vg;
        float o[8];
        #pragma unroll
        for(int p = 0; p < 4; p++){
            float lo, hi;
            upk2(a[ch][p], lo, hi);
            o[2*p  ] = fmaxf(lo + c2S[c0+2*p  ], 0.f);
            o[2*p+1] = fmaxf(hi + c2S[c0+2*p+1], 0.f);
        }
        float* dst = g_comp + (size_t)(base + slot)*128 + c0;
        *(float4*)(dst)     = make_float4(o[0], o[1], o[2], o[3]);
        *(float4*)(dst + 4) = make_float4(o[4], o[5], o[6], o[7]);
    }
}

// ---------------- kernel 5: bandwidth fill ----------------
#define SF_O     0
#define SF_IDX   16384
#define SF_FLOATS 16512   // 66048 bytes

__global__ void __launch_bounds__(256, 3) k_fill(float* __restrict__ out){
    extern __shared__ float sm[];
    float* oS = sm + SF_O;
    int* idxS = (int*)(sm + SF_IDX);

    int tid = threadIdx.x;
    int t = blockIdx.x;
    int b = t >> 11;
    int vbase = (t & 2047) << 7;
    if(tid < 128) idxS[tid] = g_index[b*G3 + vbase + tid];
    int any = __syncthreads_or(tid < 128 && idxS[tid] >= 0);

    float* ob = out + (size_t)b*128*G3 + vbase;
    float4 z4 = make_float4(0.f,0.f,0.f,0.f);
    if(!any){
        for(int i = tid; i < 4096; i += 256){
            int c = i >> 5, q = i & 31;
            __stcs((float4*)(ob + (size_t)c*G3) + q, z4);
        }
        return;
    }

    for(int i = tid; i < 4096; i += 256) ((float4*)oS)[i] = z4;
    __syncthreads();

    int cg = tid & 15, vg = tid >> 4;
    int c0 = cg*8;
    #pragma unroll
    for(int vi = 0; vi < 8; vi++){
        int v = vg*8 + vi;
        int ix = idxS[v];
        if(ix >= 0){
            const float* src = g_comp + (size_t)ix*128 + c0;
            float4 r0 = __ldg((const float4*)src);
            float4 r1 = __ldg((const float4*)(src + 4));
            int basei = (((v >> 2) ^ cg) << 2) + (v & 3);
            oS[(c0+0)*128 + basei] = r0.x;
            oS[(c0+1)*128 + basei] = r0.y;
            oS[(c0+2)*128 + basei] = r0.z;
            oS[(c0+3)*128 + basei] = r0.w;
            oS[(c0+4)*128 + basei] = r1.x;
            oS[(c0+5)*128 + basei] = r1.y;
            oS[(c0+6)*128 + basei] = r1.z;
            oS[(c0+7)*128 + basei] = r1.w;
        }
    }
    __syncthreads();

    for(int i = tid; i < 4096; i += 256){
        int c = i >> 5, vq = i & 31;
        int s = (c >> 3) & 15;
        float4 v = *(const float4*)(oS + c*128 + ((vq ^ s) << 2));
        __stcs((float4*)(ob + (size_t)c*G3) + vq, v);
    }
}

// ---------------- launch ----------------
extern "C" void kernel_launch(void* const* d_in, const int* in_sizes, int n_in,
                              void* d_out, int out_size){
    const float* pc  = (const float*)d_in[0];
    const float* W1  = (const float*)d_in[1];
    const float* b1  = (const float*)d_in[2];
    const float* g1  = (const float*)d_in[3];
    const float* be1 = (const float*)d_in[4];
    const float* rm1 = (const float*)d_in[5];
    const float* rv1 = (const float*)d_in[6];
    const float* W2  = (const float*)d_in[7];
    const float* b2  = (const float*)d_in[8];
    const float* g2  = (const float*)d_in[9];
    const float* be2 = (const float*)d_in[10];
    const float* rm2 = (const float*)d_in[11];
    const float* rv2 = (const float*)d_in[12];

    cudaFuncSetAttribute(k_gemm, cudaFuncAttributeMaxDynamicSharedMemorySize, SG_FLOATS*4);
    cudaFuncSetAttribute(k_fill, cudaFuncAttributeMaxDynamicSharedMemorySize, SF_FLOATS*4);

    k_prep<<<8448, 256>>>(W1,b1,g1,be1,rm1,rv1,W2,b2,g2,be2,rm2,rv2, pc);
    k_voxel<<<dim3(782,4), 256>>>(pc);
    k_compact<<<1024, 256>>>();
    k_gemm<<<MAXOCC/128, 256, SG_FLOATS*4>>>();
    k_fill<<<BATCH*2048, 256, SF_FLOATS*4>>>((float*)d_out);
}